// round 1
// baseline (speedup 1.0000x reference)
#include <cuda_runtime.h>

#define C      64
#define KW     21
#define T_IN   16384
#define TC     (T_IN - KW + 1)   // 16364
#define B      32
#define NB     2                 // two conv branches
#define T_TILE 64
#define N_TILES ((TC + T_TILE - 1) / T_TILE)  // 256
#define XS_W   (T_TILE + KW - 1)  // 84
#define WS_W   (4 * KW + 1)       // 85 (padded: gcd(85,32 banks)... 85%32=21, conflict-free)

// Scratch (allocation-free rule: __device__ globals)
__device__ float g_y[(size_t)NB * B * C * TC];   // 268 MB conv outputs
__device__ float g_sum[NB * C];
__device__ float g_sumsq[NB * C];
__device__ float g_scale[NB * C];
__device__ float g_shift[NB * C];
__device__ float g_feat[B * 384];

// ---------------------------------------------------------------------------
__global__ void k_init() {
    int i = threadIdx.x;
    if (i < NB * C) { g_sum[i] = 0.f; g_sumsq[i] = 0.f; }
}

// ---------------------------------------------------------------------------
// Conv1d (VALID, cross-correlation) for both branches.
// Block: 256 threads = 64 co x 4 t-groups; tile = 64 output t positions.
// x tile in smem (64ch x 84), weights staged 4-ci at a time into smem.
// Each thread: 1 co, 16 consecutive t -> 16 accumulators, 21504 FMA.
__global__ void __launch_bounds__(256) k_conv(const float* __restrict__ x,
                                              const float* __restrict__ w1,
                                              const float* __restrict__ w2) {
    const int tile = blockIdx.x, b = blockIdx.y, br = blockIdx.z;
    const float* __restrict__ w = (br == 0) ? w1 : w2;

    __shared__ float xs[C][XS_W];   // 21.5 KB
    __shared__ float ws[C][WS_W];   // 21.8 KB
    __shared__ float rs[256];
    __shared__ float rq[256];

    const int t0  = tile * T_TILE;
    const int tid = threadIdx.x;

    // load x tile (zero-pad beyond T_IN)
    const float* __restrict__ xb = x + (size_t)b * C * T_IN;
    for (int idx = tid; idx < C * XS_W; idx += 256) {
        int ci = idx / XS_W;
        int tt = idx - ci * XS_W;
        int t  = t0 + tt;
        xs[ci][tt] = (t < T_IN) ? xb[(size_t)ci * T_IN + t] : 0.f;
    }

    const int co = tid & 63;
    const int tg = tid >> 6;
    const int tb = tg * 16;

    float acc[16];
#pragma unroll
    for (int i = 0; i < 16; i++) acc[i] = 0.f;

    for (int c0 = 0; c0 < C; c0 += 4) {
        __syncthreads();  // (also covers initial xs load)
        // stage weights w[co][c0..c0+3][0..20] -> ws[co][0..83]
        for (int idx = tid; idx < C * 4 * KW; idx += 256) {
            int wco = idx / (4 * KW);
            int r   = idx - wco * (4 * KW);
            ws[wco][r] = w[wco * (C * KW) + c0 * KW + r];
        }
        __syncthreads();

#pragma unroll 1
        for (int cc = 0; cc < 4; cc++) {
            float xr[36];
#pragma unroll
            for (int i = 0; i < 9; i++)
                *(float4*)&xr[4 * i] = *(const float4*)&xs[c0 + cc][tb + 4 * i];
#pragma unroll
            for (int k = 0; k < KW; k++) {
                float wv = ws[co][cc * KW + k];
#pragma unroll
                for (int t = 0; t < 16; t++)
                    acc[t] = fmaf(wv, xr[t + k], acc[t]);
            }
        }
    }

    // write y + per-channel partial sums for batchnorm
    float lsum = 0.f, lsq = 0.f;
    float* __restrict__ yrow = g_y + (size_t)((br * B + b) * C + co) * TC;
#pragma unroll
    for (int t = 0; t < 16; t++) {
        int tt = t0 + tb + t;
        if (tt < TC) {
            yrow[tt] = acc[t];
            lsum += acc[t];
            lsq  = fmaf(acc[t], acc[t], lsq);
        }
    }
    __syncthreads();
    rs[tid] = lsum; rq[tid] = lsq;
    __syncthreads();
    if (tid < 64) {
        float s = rs[tid] + rs[tid + 64] + rs[tid + 128] + rs[tid + 192];
        float q = rq[tid] + rq[tid + 64] + rq[tid + 128] + rq[tid + 192];
        atomicAdd(&g_sum[br * C + tid], s);
        atomicAdd(&g_sumsq[br * C + tid], q);
    }
}

// ---------------------------------------------------------------------------
__global__ void k_stats(const float* __restrict__ g1, const float* __restrict__ b1,
                        const float* __restrict__ g2, const float* __restrict__ b2) {
    int i = threadIdx.x;
    if (i >= NB * C) return;
    int br = i / C, c = i - br * C;
    float n    = (float)B * (float)TC;
    float mean = g_sum[i] / n;
    float var  = g_sumsq[i] / n - mean * mean;
    float gamma = (br == 0) ? g1[c] : g2[c];
    float beta  = (br == 0) ? b1[c] : b2[c];
    float sc = rsqrtf(var + 1e-5f) * gamma;
    g_scale[i] = sc;
    g_shift[i] = beta - mean * sc;
}

// ---------------------------------------------------------------------------
// SPP: one block per (c, b, branch). Single pass over the row with BN+leakyReLU
// folded in. Branch 0 -> max pooling, branch 1 -> avg pooling.
// Level-0 bin covers [0, L); level-1 bins: [0, kern), [stride, L).
__global__ void __launch_bounds__(256) k_spp(const int* __restrict__ orig_len) {
    const int c = blockIdx.x, b = blockIdx.y, br = blockIdx.z;
    const int L      = orig_len[b] - (KW - 1);
    const int stride = L >> 1;
    const int kern   = (L + 1) >> 1;
    const float a  = g_scale[br * C + c];
    const float sh = g_shift[br * C + c];
    const float* __restrict__ row = g_y + (size_t)((br * B + b) * C + c) * TC;
    const int tid = threadIdx.x;

    __shared__ float s0[256], s1[256], s2[256];

    if (br == 0) {
        float m0 = -INFINITY, m1 = -INFINITY;
        for (int t = tid; t < L; t += 256) {
            float v = fmaf(row[t], a, sh);
            v = (v > 0.f) ? v : 0.01f * v;
            if (t < kern)   m0 = fmaxf(m0, v);
            if (t >= stride) m1 = fmaxf(m1, v);
        }
        s0[tid] = m0; s1[tid] = m1;
        __syncthreads();
        for (int off = 128; off; off >>= 1) {
            if (tid < off) {
                s0[tid] = fmaxf(s0[tid], s0[tid + off]);
                s1[tid] = fmaxf(s1[tid], s1[tid + off]);
            }
            __syncthreads();
        }
        if (tid == 0) {
            g_feat[b * 384 + c]              = fmaxf(s0[0], s1[0]);  // level 0
            g_feat[b * 384 + 64 + 2 * c]     = s0[0];
            g_feat[b * 384 + 64 + 2 * c + 1] = s1[0];
        }
    } else {
        float sa = 0.f, sb0 = 0.f, sb1 = 0.f;
        for (int t = tid; t < L; t += 256) {
            float v = fmaf(row[t], a, sh);
            v = (v > 0.f) ? v : 0.01f * v;
            sa += v;
            if (t < kern)   sb0 += v;
            if (t >= stride) sb1 += v;
        }
        s0[tid] = sa; s1[tid] = sb0; s2[tid] = sb1;
        __syncthreads();
        for (int off = 128; off; off >>= 1) {
            if (tid < off) {
                s0[tid] += s0[tid + off];
                s1[tid] += s1[tid + off];
                s2[tid] += s2[tid + off];
            }
            __syncthreads();
        }
        if (tid == 0) {
            float fk = (float)kern;
            g_feat[b * 384 + 192 + c]          = s0[0] / (float)L;  // level 0 (kern=L)
            g_feat[b * 384 + 256 + 2 * c]      = s1[0] / fk;
            g_feat[b * 384 + 256 + 2 * c + 1]  = s2[0] / fk;
        }
    }
}

// ---------------------------------------------------------------------------
__global__ void k_fc(const float* __restrict__ fc_w, const float* __restrict__ fc_b,
                     float* __restrict__ out) {
    int i = threadIdx.x;
    if (i >= B * 2) return;
    int b = i >> 1, task = i & 1;
    float acc = fc_b[task];
    const float* __restrict__ f = g_feat + b * 384;
    const float* __restrict__ w = fc_w + task * 384;
#pragma unroll 8
    for (int j = 0; j < 384; j++) acc = fmaf(f[j], w[j], acc);
    out[i] = acc;
}

// ---------------------------------------------------------------------------
extern "C" void kernel_launch(void* const* d_in, const int* in_sizes, int n_in,
                              void* d_out, int out_size) {
    const float* x        = (const float*)d_in[0];
    const int*   orig_len = (const int*)  d_in[1];
    const float* w1       = (const float*)d_in[2];
    const float* g1       = (const float*)d_in[3];
    const float* b1       = (const float*)d_in[4];
    const float* w2       = (const float*)d_in[5];
    const float* g2       = (const float*)d_in[6];
    const float* b2       = (const float*)d_in[7];
    const float* fcw      = (const float*)d_in[8];
    const float* fcb      = (const float*)d_in[9];
    float* out = (float*)d_out;

    k_init<<<1, 128>>>();
    dim3 gc(N_TILES, B, NB);
    k_conv<<<gc, 256>>>(x, w1, w2);
    k_stats<<<1, 128>>>(g1, b1, g2, b2);
    dim3 gs(C, B, NB);
    k_spp<<<gs, 256>>>(orig_len);
    k_fc<<<1, 64>>>(fcw, fcb, out);
}

// round 2
// speedup vs baseline: 1.2036x; 1.2036x over previous
#include <cuda_runtime.h>

#define C      64
#define KW     21
#define T_IN   16384
#define TC     (T_IN - KW + 1)   // 16364
#define B      32
#define NB     2
#define T_TILE 128
#define N_TILES ((TC + T_TILE - 1) / T_TILE)  // 128
#define XS2_W  (T_TILE + KW - 1)  // 148 (float2 elements per x row)
#define WS2_W  85                 // 84 used + pad (odd stride -> conflict-free)

// Scratch (allocation-free rule: __device__ globals)
__device__ float g_y[(size_t)NB * B * C * TC];   // 268 MB conv outputs
__device__ float g_sum[NB * C];
__device__ float g_sumsq[NB * C];
__device__ float g_scale[NB * C];
__device__ float g_shift[NB * C];
__device__ float g_feat[B * 384];

typedef unsigned long long u64;

__device__ __forceinline__ u64 f2u(float a, float b) {
    u64 r; asm("mov.b64 %0, {%1,%2};" : "=l"(r) : "f"(a), "f"(b)); return r;
}
__device__ __forceinline__ float2 u2f(u64 v) {
    float2 r; asm("mov.b64 {%0,%1}, %2;" : "=f"(r.x), "=f"(r.y) : "l"(v)); return r;
}

// ---------------------------------------------------------------------------
__global__ void k_init() {
    int i = threadIdx.x;
    if (i < NB * C) { g_sum[i] = 0.f; g_sumsq[i] = 0.f; }
}

// ---------------------------------------------------------------------------
// Conv1d via packed fma.rn.f32x2 (FFMA2): each thread computes 2 output
// channels (co, co+32) x 16 t positions. x tile staged into smem DUPLICATED
// as (v,v) float2 so one LDS gives the broadcast packed operand; weights
// staged prepacked as (w[co],w[co+32]).
__global__ void __launch_bounds__(256) k_conv(const float* __restrict__ x,
                                              const float* __restrict__ w1,
                                              const float* __restrict__ w2) {
    const int tile = blockIdx.x, b = blockIdx.y, br = blockIdx.z;
    const float* __restrict__ w = (br == 0) ? w1 : w2;

    extern __shared__ float2 smem[];
    float2* xs2 = smem;                       // C * XS2_W      (75.8 KB)
    float2* ws2 = xs2 + C * XS2_W;            // 32 * WS2_W     (21.8 KB)
    float2* rs2 = ws2 + 32 * WS2_W;           // 256            ( 2 KB)
    float2* rq2 = rs2 + 256;                  // 256            ( 2 KB)

    const int t0  = tile * T_TILE;
    const int tid = threadIdx.x;

    // stage x tile, duplicated lanes (zero-pad beyond T_IN)
    const float* __restrict__ xb = x + (size_t)b * C * T_IN;
    for (int idx = tid; idx < C * XS2_W; idx += 256) {
        int ci = idx / XS2_W;
        int tt = idx - ci * XS2_W;
        int t  = t0 + tt;
        float v = (t < T_IN) ? xb[(size_t)ci * T_IN + t] : 0.f;
        xs2[idx] = make_float2(v, v);
    }

    const int tp = tid & 31;   // co pair: coA = tp, coB = tp + 32
    const int tg = tid >> 5;   // t-group 0..7
    const int tb = tg * 16;

    u64 acc[16];
#pragma unroll
    for (int i = 0; i < 16; i++) acc[i] = 0ull;

#pragma unroll 1
    for (int c0 = 0; c0 < C; c0 += 4) {
        __syncthreads();  // xs ready (1st iter) / prev reads done before ws overwrite
        // stage packed weights: ws2[p][cc*21+k] = (w[p][c0+cc][k], w[p+32][c0+cc][k])
        for (int idx = tid; idx < 32 * 84; idx += 256) {
            int p  = idx / 84;
            int r  = idx - p * 84;          // r = cc*21 + k
            int cc = r / 21;
            int k  = r - cc * 21;
            int wo = (c0 + cc) * KW + k;
            ws2[p * WS2_W + r] = make_float2(w[p * (C * KW) + wo],
                                             w[(p + 32) * (C * KW) + wo]);
        }
        __syncthreads();

#pragma unroll 1
        for (int cc = 0; cc < 4; cc++) {
            // 36 packed x operands (broadcast LDS.128: 2 per load)
            u64 xr[36];
            const float4* __restrict__ x4 =
                (const float4*)(xs2 + (c0 + cc) * XS2_W + tb);
#pragma unroll
            for (int i = 0; i < 18; i++) {
                float4 v = x4[i];
                xr[2 * i]     = f2u(v.x, v.y);
                xr[2 * i + 1] = f2u(v.z, v.w);
            }
            const float2* __restrict__ wrow = ws2 + tp * WS2_W + cc * 21;
#pragma unroll
            for (int k = 0; k < KW; k++) {
                float2 wv2 = wrow[k];
                u64 wv = f2u(wv2.x, wv2.y);
#pragma unroll
                for (int t = 0; t < 16; t++)
                    asm("fma.rn.f32x2 %0, %1, %2, %0;"
                        : "+l"(acc[t]) : "l"(wv), "l"(xr[t + k]));
            }
        }
    }

    // write y (two rows) + per-channel partial sums for batchnorm
    float lsA = 0.f, lsB = 0.f, lqA = 0.f, lqB = 0.f;
    const size_t rbase = (size_t)((br * B + b) * C);
    float* __restrict__ rowA = g_y + (rbase + tp) * TC;
    float* __restrict__ rowB = g_y + (rbase + tp + 32) * TC;
#pragma unroll
    for (int t = 0; t < 16; t++) {
        int tt = t0 + tb + t;
        if (tt < TC) {
            float2 v = u2f(acc[t]);
            rowA[tt] = v.x;
            rowB[tt] = v.y;
            lsA += v.x;  lqA = fmaf(v.x, v.x, lqA);
            lsB += v.y;  lqB = fmaf(v.y, v.y, lqB);
        }
    }
    __syncthreads();
    rs2[tid] = make_float2(lsA, lsB);
    rq2[tid] = make_float2(lqA, lqB);
    __syncthreads();
    if (tid < 32) {
        float sA = 0.f, sB = 0.f, qA = 0.f, qB = 0.f;
#pragma unroll
        for (int g = 0; g < 8; g++) {
            float2 s = rs2[g * 32 + tid];
            float2 q = rq2[g * 32 + tid];
            sA += s.x; sB += s.y; qA += q.x; qB += q.y;
        }
        atomicAdd(&g_sum[br * C + tid],        sA);
        atomicAdd(&g_sum[br * C + tid + 32],   sB);
        atomicAdd(&g_sumsq[br * C + tid],      qA);
        atomicAdd(&g_sumsq[br * C + tid + 32], qB);
    }
}

// ---------------------------------------------------------------------------
__global__ void k_stats(const float* __restrict__ g1, const float* __restrict__ b1,
                        const float* __restrict__ g2, const float* __restrict__ b2) {
    int i = threadIdx.x;
    if (i >= NB * C) return;
    int br = i / C, c = i - br * C;
    float n    = (float)B * (float)TC;
    float mean = g_sum[i] / n;
    float var  = g_sumsq[i] / n - mean * mean;
    float gamma = (br == 0) ? g1[c] : g2[c];
    float beta  = (br == 0) ? b1[c] : b2[c];
    float sc = rsqrtf(var + 1e-5f) * gamma;
    g_scale[i] = sc;
    g_shift[i] = beta - mean * sc;
}

// ---------------------------------------------------------------------------
// SPP: one block per (c, b, branch). Single pass with BN+leakyReLU folded in.
__global__ void __launch_bounds__(256) k_spp(const int* __restrict__ orig_len) {
    const int c = blockIdx.x, b = blockIdx.y, br = blockIdx.z;
    const int L      = orig_len[b] - (KW - 1);
    const int stride = L >> 1;
    const int kern   = (L + 1) >> 1;
    const float a  = g_scale[br * C + c];
    const float sh = g_shift[br * C + c];
    const float* __restrict__ row = g_y + (size_t)((br * B + b) * C + c) * TC;
    const int tid = threadIdx.x;

    __shared__ float s0[256], s1[256], s2[256];

    if (br == 0) {
        float m0 = -INFINITY, m1 = -INFINITY;
        for (int t = tid; t < L; t += 256) {
            float v = fmaf(row[t], a, sh);
            v = (v > 0.f) ? v : 0.01f * v;
            if (t < kern)    m0 = fmaxf(m0, v);
            if (t >= stride) m1 = fmaxf(m1, v);
        }
        s0[tid] = m0; s1[tid] = m1;
        __syncthreads();
        for (int off = 128; off; off >>= 1) {
            if (tid < off) {
                s0[tid] = fmaxf(s0[tid], s0[tid + off]);
                s1[tid] = fmaxf(s1[tid], s1[tid + off]);
            }
            __syncthreads();
        }
        if (tid == 0) {
            g_feat[b * 384 + c]              = fmaxf(s0[0], s1[0]);  // level 0
            g_feat[b * 384 + 64 + 2 * c]     = s0[0];
            g_feat[b * 384 + 64 + 2 * c + 1] = s1[0];
        }
    } else {
        float sa = 0.f, sb0 = 0.f, sb1 = 0.f;
        for (int t = tid; t < L; t += 256) {
            float v = fmaf(row[t], a, sh);
            v = (v > 0.f) ? v : 0.01f * v;
            sa += v;
            if (t < kern)    sb0 += v;
            if (t >= stride) sb1 += v;
        }
        s0[tid] = sa; s1[tid] = sb0; s2[tid] = sb1;
        __syncthreads();
        for (int off = 128; off; off >>= 1) {
            if (tid < off) {
                s0[tid] += s0[tid + off];
                s1[tid] += s1[tid + off];
                s2[tid] += s2[tid + off];
            }
            __syncthreads();
        }
        if (tid == 0) {
            float fk = (float)kern;
            g_feat[b * 384 + 192 + c]         = s0[0] / (float)L;   // level 0
            g_feat[b * 384 + 256 + 2 * c]     = s1[0] / fk;
            g_feat[b * 384 + 256 + 2 * c + 1] = s2[0] / fk;
        }
    }
}

// ---------------------------------------------------------------------------
__global__ void k_fc(const float* __restrict__ fc_w, const float* __restrict__ fc_b,
                     float* __restrict__ out) {
    int i = threadIdx.x;
    if (i >= B * 2) return;
    int b = i >> 1, task = i & 1;
    float acc = fc_b[task];
    const float* __restrict__ f = g_feat + b * 384;
    const float* __restrict__ w = fc_w + task * 384;
#pragma unroll 8
    for (int j = 0; j < 384; j++) acc = fmaf(f[j], w[j], acc);
    out[i] = acc;
}

// ---------------------------------------------------------------------------
extern "C" void kernel_launch(void* const* d_in, const int* in_sizes, int n_in,
                              void* d_out, int out_size) {
    const float* x        = (const float*)d_in[0];
    const int*   orig_len = (const int*)  d_in[1];
    const float* w1       = (const float*)d_in[2];
    const float* g1       = (const float*)d_in[3];
    const float* b1       = (const float*)d_in[4];
    const float* w2       = (const float*)d_in[5];
    const float* g2       = (const float*)d_in[6];
    const float* b2       = (const float*)d_in[7];
    const float* fcw      = (const float*)d_in[8];
    const float* fcb      = (const float*)d_in[9];
    float* out = (float*)d_out;

    const int smem_bytes = (C * XS2_W + 32 * WS2_W + 512) * sizeof(float2);
    cudaFuncSetAttribute(k_conv, cudaFuncAttributeMaxDynamicSharedMemorySize,
                         smem_bytes);

    k_init<<<1, 128>>>();
    dim3 gc(N_TILES, B, NB);
    k_conv<<<gc, 256, smem_bytes>>>(x, w1, w2);
    k_stats<<<1, 128>>>(g1, b1, g2, b2);
    dim3 gs(C, B, NB);
    k_spp<<<gs, 256>>>(orig_len);
    k_fc<<<1, 64>>>(fcw, fcb, out);
}

// round 4
// speedup vs baseline: 2.9807x; 2.4765x over previous
#include <cuda_runtime.h>
#include <cuda_bf16.h>
#include <cstdint>

#define C      64
#define KW     21
#define T_IN   16384
#define TC     (T_IN - KW + 1)   // 16364
#define B      32
#define MT     128
#define NTILES 128               // t tiles
#define TROWS  16512             // padded transposed-x rows (129*128)
#define TSPLIT 8

// smem layout constants (bytes)
#define XS_B    21312            // 148 rows * 144B per split
#define WB_OFF  42624            // after xhi+xlo
#define WB_STR  36864            // per double-buffer (hi+lo)
#define WLO_OFF 18432            // lo half inside a wbuf
#define SMEM_TOTAL 116352        // 42624 + 2*36864

// ---------------- device scratch (no allocations allowed) -------------------
__device__ uint4 g_wh[21 * 1024];                // W images [k][n=128][ci=64] bf16-hi
__device__ uint4 g_wl[21 * 1024];
__device__ uint4 g_xh[(size_t)B * TROWS * 8];    // X transposed [b][t][ci] bf16-hi
__device__ uint4 g_xl[(size_t)B * TROWS * 8];
__device__ float g_y[(size_t)B * 16384 * 128];   // conv out [b][t][n]  (268MB)
__device__ float g_sum[128];
__device__ float g_sumsq[128];
__device__ float g_scale[128];
__device__ float g_shift[128];
__device__ float g_part[B * TSPLIT * 3 * 128];
__device__ float g_feat[B * 384];

// ---------------- helpers ----------------------------------------------------
__device__ __forceinline__ uint32_t smem_u32(const void* p) {
    uint32_t a;
    asm("{ .reg .u64 t; cvta.to.shared.u64 t, %1; cvt.u32.u64 %0, t; }" : "=r"(a) : "l"(p));
    return a;
}
__device__ __forceinline__ void cpa16(uint32_t dst, const void* src) {
    asm volatile("cp.async.cg.shared.global [%0], [%1], 16;" :: "r"(dst), "l"(src));
}
#define CP_COMMIT() asm volatile("cp.async.commit_group;" ::: "memory")
#define CP_WAIT0()  asm volatile("cp.async.wait_group 0;" ::: "memory")

__device__ __forceinline__ void ldsm4(uint32_t* r, uint32_t a) {
    asm volatile("ldmatrix.sync.aligned.m8n8.x4.shared.b16 {%0,%1,%2,%3}, [%4];"
                 : "=r"(r[0]), "=r"(r[1]), "=r"(r[2]), "=r"(r[3]) : "r"(a));
}
__device__ __forceinline__ void mma16816(float* d, const uint32_t* a, const uint32_t* b2) {
    asm volatile(
        "mma.sync.aligned.m16n8k16.row.col.f32.bf16.bf16.f32 "
        "{%0,%1,%2,%3},{%4,%5,%6,%7},{%8,%9},{%0,%1,%2,%3};"
        : "+f"(d[0]), "+f"(d[1]), "+f"(d[2]), "+f"(d[3])
        : "r"(a[0]), "r"(a[1]), "r"(a[2]), "r"(a[3]), "r"(b2[0]), "r"(b2[1]));
}
__device__ __forceinline__ uint32_t pack_hi(float a, float b) {
    __nv_bfloat16 ha = __float2bfloat16(a), hb = __float2bfloat16(b);
    return (uint32_t)__bfloat16_as_ushort(ha) | ((uint32_t)__bfloat16_as_ushort(hb) << 16);
}
__device__ __forceinline__ uint32_t pack_lo(float a, float b) {
    __nv_bfloat16 ha = __float2bfloat16(a), hb = __float2bfloat16(b);
    return pack_hi(a - __bfloat162float(ha), b - __bfloat162float(hb));
}

// ---------------------------------------------------------------------------
__global__ void k_init() {
    int i = threadIdx.x;
    if (i < 128) { g_sum[i] = 0.f; g_sumsq[i] = 0.f; }
}

// W images: [k][n][ci] bf16 rows of 128B (n<64: w1, else w2)
__global__ void k_prepw(const float* __restrict__ w1, const float* __restrict__ w2) {
    int k = blockIdx.x;
    uint32_t* dh = (uint32_t*)g_wh;
    uint32_t* dl = (uint32_t*)g_wl;
    for (int idx = threadIdx.x; idx < 128 * 32; idx += 256) {
        int n = idx >> 5, p = idx & 31, ci = 2 * p;
        const float* src = (n < 64) ? (w1 + ((size_t)n * C + ci) * KW + k)
                                    : (w2 + ((size_t)(n - 64) * C + ci) * KW + k);
        float a = src[0], c2 = src[KW];
        dh[(k * 128 + n) * 32 + p] = pack_hi(a, c2);
        dl[(k * 128 + n) * 32 + p] = pack_lo(a, c2);
    }
}

// X transpose -> [b][t][ci] bf16 hi/lo, zero-padded past T_IN
__global__ void __launch_bounds__(256) k_prepx(const float* __restrict__ x) {
    __shared__ float smx[64][129];
    int b = blockIdx.y, t0 = blockIdx.x * 128;
    for (int idx = threadIdx.x; idx < 64 * 128; idx += 256) {
        int ci = idx >> 7, tt = idx & 127;
        int t = t0 + tt;
        smx[ci][tt] = (t < T_IN) ? x[((size_t)b * C + ci) * T_IN + t] : 0.f;
    }
    __syncthreads();
    uint32_t* dh = (uint32_t*)g_xh;
    uint32_t* dl = (uint32_t*)g_xl;
    for (int idx = threadIdx.x; idx < 128 * 32; idx += 256) {
        int tt = idx >> 5, p = idx & 31;
        float a = smx[2 * p][tt], c2 = smx[2 * p + 1][tt];
        size_t gi = ((size_t)b * TROWS + t0 + tt) * 32 + p;
        dh[gi] = pack_hi(a, c2);
        dl[gi] = pack_lo(a, c2);
    }
}

// ---------------------------------------------------------------------------
__device__ __forceinline__ void stage_w(uint32_t wb_u, char* /*unused*/, int k, int buf, int tid) {
    const uint4* sh = g_wh + (size_t)k * 1024;
    const uint4* sl = g_wl + (size_t)k * 1024;
    uint32_t base = wb_u + buf * WB_STR;
    for (int i = tid; i < 2048; i += 256) {
        int split = i >> 10;
        int j = i & 1023;
        int r = j >> 3, c2 = j & 7;
        uint32_t d = base + split * WLO_OFF + r * 144 + c2 * 16;
        cpa16(d, (split ? sl : sh) + j);
    }
}

// Main mma.sync conv kernel: block (tile, b), 256 threads = 8 warps (2m x 4n),
// warp tile 64x32, D[t=128][n=128] in registers.
__global__ void __launch_bounds__(256) k_conv() {
    extern __shared__ __align__(1024) char sm[];
    const int tile = blockIdx.x, b = blockIdx.y;
    const int t0 = tile * MT;
    const int tid = threadIdx.x;
    const int wid = tid >> 5, lane = tid & 31;
    const int wm = wid & 1, wn = wid >> 1;

    const uint32_t sm_u = smem_u32(sm);
    const uint32_t xs_h = sm_u, xs_l = sm_u + XS_B;
    const uint32_t wb_u = sm_u + WB_OFF;

    // stage X tile (hi+lo, 148 rows) + W k=0 via cp.async
    {
        const uint4* sxh = g_xh + ((size_t)b * TROWS + t0) * 8;
        const uint4* sxl = g_xl + ((size_t)b * TROWS + t0) * 8;
        for (int i = tid; i < 2368; i += 256) {
            int split = (i >= 1184);
            int j = i - split * 1184;
            int r = j >> 3, c2 = j & 7;
            uint32_t d = (split ? xs_l : xs_h) + r * 144 + c2 * 16;
            cpa16(d, (split ? sxl : sxh) + j);
        }
        stage_w(wb_u, sm, 0, 0, tid);
        CP_COMMIT();
    }

    // per-warp ldmatrix base addresses
    uint32_t cA[4];   // A frag bases (add split off, k*144, ks*32)
#pragma unroll
    for (int i = 0; i < 4; i++)
        cA[i] = (uint32_t)((wm * 64 + i * 16 + (lane & 15)) * 144 + ((lane >> 4) * 16));
    uint32_t cB[2];
#pragma unroll
    for (int p = 0; p < 2; p++)
        cB[p] = (uint32_t)((wn * 32 + p * 16 + ((lane >> 4) << 3) + (lane & 7)) * 144 +
                           (((lane >> 3) & 1) * 16));

    float acc[4][4][4];
#pragma unroll
    for (int i = 0; i < 4; i++)
#pragma unroll
        for (int j = 0; j < 4; j++)
#pragma unroll
            for (int e = 0; e < 4; e++) acc[i][j][e] = 0.f;

    CP_WAIT0();
    __syncthreads();

#pragma unroll 1
    for (int k = 0; k < KW; k++) {
        const int buf = k & 1;
        if (k + 1 < KW) { stage_w(wb_u, sm, k + 1, buf ^ 1, tid); CP_COMMIT(); }

        const uint32_t axh = xs_h + k * 144;
        const uint32_t axl = xs_l + k * 144;
        const uint32_t bwh = wb_u + buf * WB_STR;
        const uint32_t bwl = bwh + WLO_OFF;

#pragma unroll
        for (int ks = 0; ks < 4; ks++) {
            uint32_t ah[4][4], al[4][4], bh[2][4], bl[2][4];
#pragma unroll
            for (int i = 0; i < 4; i++) {
                ldsm4(ah[i], axh + cA[i] + ks * 32);
                ldsm4(al[i], axl + cA[i] + ks * 32);
            }
#pragma unroll
            for (int p = 0; p < 2; p++) {
                ldsm4(bh[p], bwh + cB[p] + ks * 32);
                ldsm4(bl[p], bwl + cB[p] + ks * 32);
            }
#pragma unroll
            for (int i = 0; i < 4; i++)
#pragma unroll
                for (int j = 0; j < 4; j++) {
                    const uint32_t* bhf = &bh[j >> 1][(j & 1) * 2];
                    const uint32_t* blf = &bl[j >> 1][(j & 1) * 2];
                    mma16816(acc[i][j], ah[i], bhf);
                    mma16816(acc[i][j], al[i], bhf);
                    mma16816(acc[i][j], ah[i], blf);
                }
        }
        if (k + 1 < KW) CP_WAIT0();
        __syncthreads();
    }

    // Epilogue: acc -> smem [t][n] (stride 136 floats), BN sums, coalesced store
    float* ep = (float*)(sm + WB_OFF);
#pragma unroll
    for (int i = 0; i < 4; i++) {
        int tl = wm * 64 + i * 16 + (lane >> 2);
#pragma unroll
        for (int j = 0; j < 4; j++) {
            int nn = wn * 32 + j * 8 + (lane & 3) * 2;
            *(float2*)&ep[tl * 136 + nn]       = make_float2(acc[i][j][0], acc[i][j][1]);
            *(float2*)&ep[(tl + 8) * 136 + nn] = make_float2(acc[i][j][2], acc[i][j][3]);
        }
    }
    __syncthreads();
    if (tid < 128) {
        float s = 0.f, q = 0.f;
        for (int t = 0; t < 128; t++) {
            if (t0 + t < TC) {
                float v = ep[t * 136 + tid];
                s += v; q = fmaf(v, v, q);
            }
        }
        atomicAdd(&g_sum[tid], s);
        atomicAdd(&g_sumsq[tid], q);
    }
    float* ybase = g_y + ((size_t)b * 16384 + t0) * 128;
    for (int i = tid; i < 4096; i += 256) {
        int t = i >> 5, c4 = i & 31;
        *(float4*)&ybase[(size_t)t * 128 + c4 * 4] = *(float4*)&ep[t * 136 + c4 * 4];
    }
}

// ---------------------------------------------------------------------------
__global__ void k_stats(const float* __restrict__ g1, const float* __restrict__ b1,
                        const float* __restrict__ g2, const float* __restrict__ b2) {
    int i = threadIdx.x;
    if (i >= 128) return;
    int br = i >> 6, c = i & 63;
    float n = (float)B * (float)TC;
    float mean = g_sum[i] / n;
    float var = g_sumsq[i] / n - mean * mean;
    float gamma = (br == 0) ? g1[c] : g2[c];
    float beta  = (br == 0) ? b1[c] : b2[c];
    float sc = rsqrtf(var + 1e-5f) * gamma;
    g_scale[i] = sc;
    g_shift[i] = beta - mean * sc;
}

// ---------------------------------------------------------------------------
// SPP partial pass over g_y [b][t][n], n-contiguous (coalesced).
__global__ void __launch_bounds__(256) k_spp(const int* __restrict__ orig_len) {
    const int s = blockIdx.x, b = blockIdx.y;
    const int L = orig_len[b] - (KW - 1);
    const int stride = L >> 1, kern = (L + 1) >> 1;
    const int chunk = (L + TSPLIT - 1) / TSPLIT;
    const int tb = s * chunk;
    const int te = min(L, tb + chunk);
    const int n = threadIdx.x & 127, h = threadIdx.x >> 7;
    const float a = g_scale[n], sh = g_shift[n];
    const float* __restrict__ base = g_y + (size_t)b * 16384 * 128 + n;

    __shared__ float r0[256], r1[256], r2[256];
    float e0, e1, e2;
    if (n < 64) {
        float m0 = -INFINITY, m1 = -INFINITY;
        for (int t = tb + h; t < te; t += 2) {
            float v = fmaf(base[(size_t)t * 128], a, sh);
            v = (v > 0.f) ? v : 0.01f * v;
            if (t < kern)    m0 = fmaxf(m0, v);
            if (t >= stride) m1 = fmaxf(m1, v);
        }
        e0 = m0; e1 = m1; e2 = 0.f;
    } else {
        float sa = 0.f, s0 = 0.f, s1 = 0.f;
        for (int t = tb + h; t < te; t += 2) {
            float v = fmaf(base[(size_t)t * 128], a, sh);
            v = (v > 0.f) ? v : 0.01f * v;
            sa += v;
            if (t < kern)    s0 += v;
            if (t >= stride) s1 += v;
        }
        e0 = sa; e1 = s0; e2 = s1;
    }
    r0[threadIdx.x] = e0; r1[threadIdx.x] = e1; r2[threadIdx.x] = e2;
    __syncthreads();
    if (h == 0) {
        int o = threadIdx.x + 128;
        if (n < 64) { e0 = fmaxf(e0, r0[o]); e1 = fmaxf(e1, r1[o]); e2 = 0.f; }
        else        { e0 += r0[o]; e1 += r1[o]; e2 += r2[o]; }
        float* p = g_part + (size_t)(b * TSPLIT + s) * 384;
        p[n] = e0; p[128 + n] = e1; p[256 + n] = e2;
    }
}

__global__ void k_spp2(const int* __restrict__ orig_len) {
    int b = blockIdx.x, n = threadIdx.x;
    if (n >= 128) return;
    int L = orig_len[b] - (KW - 1);
    int kern = (L + 1) >> 1;
    const float* p = g_part + (size_t)b * TSPLIT * 384;
    if (n < 64) {
        float m0 = -INFINITY, m1 = -INFINITY;
        for (int s = 0; s < TSPLIT; s++) {
            m0 = fmaxf(m0, p[s * 384 + n]);
            m1 = fmaxf(m1, p[s * 384 + 128 + n]);
        }
        g_feat[b * 384 + n] = fmaxf(m0, m1);
        g_feat[b * 384 + 64 + 2 * n] = m0;
        g_feat[b * 384 + 65 + 2 * n] = m1;
    } else {
        int c = n - 64;
        float sa = 0.f, s0 = 0.f, s1 = 0.f;
        for (int s = 0; s < TSPLIT; s++) {
            sa += p[s * 384 + n];
            s0 += p[s * 384 + 128 + n];
            s1 += p[s * 384 + 256 + n];
        }
        g_feat[b * 384 + 192 + c] = sa / (float)L;
        g_feat[b * 384 + 256 + 2 * c] = s0 / (float)kern;
        g_feat[b * 384 + 257 + 2 * c] = s1 / (float)kern;
    }
}

// ---------------------------------------------------------------------------
__global__ void k_fc(const float* __restrict__ fc_w, const float* __restrict__ fc_b,
                     float* __restrict__ out) {
    int i = threadIdx.x;
    if (i >= B * 2) return;
    int b = i >> 1, task = i & 1;
    float acc = fc_b[task];
    const float* __restrict__ f = g_feat + b * 384;
    const float* __restrict__ w = fc_w + task * 384;
#pragma unroll 8
    for (int j = 0; j < 384; j++) acc = fmaf(f[j], w[j], acc);
    out[i] = acc;
}

// ---------------------------------------------------------------------------
extern "C" void kernel_launch(void* const* d_in, const int* in_sizes, int n_in,
                              void* d_out, int out_size) {
    const float* x        = (const float*)d_in[0];
    const int*   orig_len = (const int*)  d_in[1];
    const float* w1       = (const float*)d_in[2];
    const float* g1       = (const float*)d_in[3];
    const float* b1       = (const float*)d_in[4];
    const float* w2       = (const float*)d_in[5];
    const float* g2       = (const float*)d_in[6];
    const float* b2       = (const float*)d_in[7];
    const float* fcw      = (const float*)d_in[8];
    const float* fcb      = (const float*)d_in[9];
    float* out = (float*)d_out;

    cudaFuncSetAttribute(k_conv, cudaFuncAttributeMaxDynamicSharedMemorySize,
                         SMEM_TOTAL);

    k_init<<<1, 128>>>();
    k_prepw<<<21, 256>>>(w1, w2);
    dim3 gx(TROWS / 128, B);
    k_prepx<<<gx, 256>>>(x);
    dim3 gc(NTILES, B);
    k_conv<<<gc, 256, SMEM_TOTAL>>>();
    k_stats<<<1, 128>>>(g1, b1, g2, b2);
    dim3 gs(TSPLIT, B);
    k_spp<<<gs, 256>>>(orig_len);
    k_spp2<<<B, 128>>>(orig_len);
    k_fc<<<1, 64>>>(fcw, fcb, out);
}

// round 5
// speedup vs baseline: 4.3090x; 1.4457x over previous
#include <cuda_runtime.h>
#include <cuda_fp16.h>
#include <cstdint>

#define C      64
#define KW     21
#define T_IN   16384
#define TC     (T_IN - KW + 1)   // 16364
#define B      32
#define MT     128
#define NTILES 128               // t tiles
#define TROWS  16512             // padded transposed-x rows (129*128)
#define TSPLIT 8

// smem layout (bytes): xh[21312] xl[21312] wbuf0[18432] wbuf1[18432]
#define XS_B    21312            // 148 rows * 144B per split
#define WB_OFF  42624
#define WB_STR  18432            // 128 rows * 144B (hi only)
#define SMEM_TOTAL 79488

// ---------------- device scratch (no allocations allowed) -------------------
__device__ uint4 g_wh[21 * 1024];                // W images [k][n=128][ci=64] fp16-hi
__device__ uint4 g_xh[(size_t)B * TROWS * 8];    // X transposed [b][t][ci] fp16-hi
__device__ uint4 g_xl[(size_t)B * TROWS * 8];    // fp16 residual (x - xh, exact)
__device__ float g_y[(size_t)B * 16384 * 128];   // conv out [b][t][n]  (268MB)
__device__ float g_sum[128];
__device__ float g_sumsq[128];
__device__ float g_scale[128];
__device__ float g_shift[128];
__device__ float g_part[B * TSPLIT * 3 * 128];
__device__ float g_feat[B * 384];

// ---------------- helpers ----------------------------------------------------
__device__ __forceinline__ uint32_t smem_u32(const void* p) {
    uint32_t a;
    asm("{ .reg .u64 t; cvta.to.shared.u64 t, %1; cvt.u32.u64 %0, t; }" : "=r"(a) : "l"(p));
    return a;
}
__device__ __forceinline__ void cpa16(uint32_t dst, const void* src) {
    asm volatile("cp.async.cg.shared.global [%0], [%1], 16;" :: "r"(dst), "l"(src));
}
#define CP_COMMIT() asm volatile("cp.async.commit_group;" ::: "memory")
#define CP_WAIT0()  asm volatile("cp.async.wait_group 0;" ::: "memory")

__device__ __forceinline__ void ldsm4(uint32_t* r, uint32_t a) {
    asm volatile("ldmatrix.sync.aligned.m8n8.x4.shared.b16 {%0,%1,%2,%3}, [%4];"
                 : "=r"(r[0]), "=r"(r[1]), "=r"(r[2]), "=r"(r[3]) : "r"(a));
}
__device__ __forceinline__ void mma16816(float* d, const uint32_t* a, const uint32_t* b2) {
    asm volatile(
        "mma.sync.aligned.m16n8k16.row.col.f32.f16.f16.f32 "
        "{%0,%1,%2,%3},{%4,%5,%6,%7},{%8,%9},{%0,%1,%2,%3};"
        : "+f"(d[0]), "+f"(d[1]), "+f"(d[2]), "+f"(d[3])
        : "r"(a[0]), "r"(a[1]), "r"(a[2]), "r"(a[3]), "r"(b2[0]), "r"(b2[1]));
}
__device__ __forceinline__ uint32_t pack_h(float a, float b) {
    __half ha = __float2half_rn(a), hb = __float2half_rn(b);
    return (uint32_t)__half_as_ushort(ha) | ((uint32_t)__half_as_ushort(hb) << 16);
}
__device__ __forceinline__ uint32_t pack_l(float a, float b) {
    __half ha = __float2half_rn(a), hb = __float2half_rn(b);
    return pack_h(a - __half2float(ha), b - __half2float(hb));
}

// ---------------------------------------------------------------------------
__global__ void k_init() {
    int i = threadIdx.x;
    if (i < 128) { g_sum[i] = 0.f; g_sumsq[i] = 0.f; }
}

// W images: [k][n][ci] fp16 rows of 128B (n<64: w1, else w2)
__global__ void k_prepw(const float* __restrict__ w1, const float* __restrict__ w2) {
    int k = blockIdx.x;
    uint32_t* dh = (uint32_t*)g_wh;
    for (int idx = threadIdx.x; idx < 128 * 32; idx += 256) {
        int n = idx >> 5, p = idx & 31, ci = 2 * p;
        const float* src = (n < 64) ? (w1 + ((size_t)n * C + ci) * KW + k)
                                    : (w2 + ((size_t)(n - 64) * C + ci) * KW + k);
        dh[(k * 128 + n) * 32 + p] = pack_h(src[0], src[KW]);
    }
}

// X transpose -> [b][t][ci] fp16 hi/lo (Dekker split: hi+lo == x exactly)
__global__ void __launch_bounds__(256) k_prepx(const float* __restrict__ x) {
    __shared__ float smx[64][129];
    int b = blockIdx.y, t0 = blockIdx.x * 128;
    for (int idx = threadIdx.x; idx < 64 * 128; idx += 256) {
        int ci = idx >> 7, tt = idx & 127;
        int t = t0 + tt;
        smx[ci][tt] = (t < T_IN) ? x[((size_t)b * C + ci) * T_IN + t] : 0.f;
    }
    __syncthreads();
    uint32_t* dh = (uint32_t*)g_xh;
    uint32_t* dl = (uint32_t*)g_xl;
    for (int idx = threadIdx.x; idx < 128 * 32; idx += 256) {
        int tt = idx >> 5, p = idx & 31;
        float a = smx[2 * p][tt], c2 = smx[2 * p + 1][tt];
        size_t gi = ((size_t)b * TROWS + t0 + tt) * 32 + p;
        dh[gi] = pack_h(a, c2);
        dl[gi] = pack_l(a, c2);
    }
}

// ---------------------------------------------------------------------------
__device__ __forceinline__ void stage_w(uint32_t wb_u, int k, int buf, int tid) {
    const uint4* sh = g_wh + (size_t)k * 1024;
    uint32_t base = wb_u + buf * WB_STR;
    for (int i = tid; i < 1024; i += 256) {
        int r = i >> 3, c2 = i & 7;
        cpa16(base + r * 144 + c2 * 16, sh + i);
    }
}

// Main mma.sync conv: block (tile, b), 256 threads = 8 warps (2m x 4n),
// warp tile 64x32, D[t=128][n=128] in registers. fp16 2-product split.
__global__ void __launch_bounds__(256, 2) k_conv() {
    extern __shared__ __align__(1024) char sm[];
    const int tile = blockIdx.x, b = blockIdx.y;
    const int t0 = tile * MT;
    const int tid = threadIdx.x;
    const int wid = tid >> 5, lane = tid & 31;
    const int wm = wid & 1, wn = wid >> 1;

    const uint32_t sm_u = smem_u32(sm);
    const uint32_t xs_h = sm_u, xs_l = sm_u + XS_B;
    const uint32_t wb_u = sm_u + WB_OFF;

    // stage X tile (hi+lo, 148 rows) + W k=0 via cp.async
    {
        const uint4* sxh = g_xh + ((size_t)b * TROWS + t0) * 8;
        const uint4* sxl = g_xl + ((size_t)b * TROWS + t0) * 8;
        for (int i = tid; i < 2368; i += 256) {
            int split = (i >= 1184);
            int j = i - split * 1184;
            int r = j >> 3, c2 = j & 7;
            uint32_t d = (split ? xs_l : xs_h) + r * 144 + c2 * 16;
            cpa16(d, (split ? sxl : sxh) + j);
        }
        stage_w(wb_u, 0, 0, tid);
        CP_COMMIT();
    }

    // per-warp ldmatrix base addresses
    uint32_t cA[4];
#pragma unroll
    for (int i = 0; i < 4; i++)
        cA[i] = (uint32_t)((wm * 64 + i * 16 + (lane & 15)) * 144 + ((lane >> 4) * 16));
    uint32_t cB[2];
#pragma unroll
    for (int p = 0; p < 2; p++)
        cB[p] = (uint32_t)((wn * 32 + p * 16 + ((lane >> 4) << 3) + (lane & 7)) * 144 +
                           (((lane >> 3) & 1) * 16));

    float acc[4][4][4];
#pragma unroll
    for (int i = 0; i < 4; i++)
#pragma unroll
        for (int j = 0; j < 4; j++)
#pragma unroll
            for (int e = 0; e < 4; e++) acc[i][j][e] = 0.f;

    CP_WAIT0();
    __syncthreads();

#pragma unroll 1
    for (int k = 0; k < KW; k++) {
        const int buf = k & 1;
        if (k + 1 < KW) { stage_w(wb_u, k + 1, buf ^ 1, tid); CP_COMMIT(); }

        const uint32_t axh = xs_h + k * 144;
        const uint32_t axl = xs_l + k * 144;
        const uint32_t bwh = wb_u + buf * WB_STR;

#pragma unroll
        for (int ks = 0; ks < 4; ks++) {
            uint32_t ah[4][4], al[4][4], bh[2][4];
#pragma unroll
            for (int i = 0; i < 4; i++) {
                ldsm4(ah[i], axh + cA[i] + ks * 32);
                ldsm4(al[i], axl + cA[i] + ks * 32);
            }
#pragma unroll
            for (int p = 0; p < 2; p++) ldsm4(bh[p], bwh + cB[p] + ks * 32);
#pragma unroll
            for (int i = 0; i < 4; i++)
#pragma unroll
                for (int j = 0; j < 4; j++) {
                    const uint32_t* bf = &bh[j >> 1][(j & 1) * 2];
                    mma16816(acc[i][j], ah[i], bf);
                    mma16816(acc[i][j], al[i], bf);
                }
        }
        if (k + 1 < KW) CP_WAIT0();
        __syncthreads();
    }

    // Epilogue: acc -> smem [t][n] (stride 136 floats; aliases X+W regions),
    // BN partial sums, coalesced STG of y.
    float* ep = (float*)sm;
#pragma unroll
    for (int i = 0; i < 4; i++) {
        int tl = wm * 64 + i * 16 + (lane >> 2);
#pragma unroll
        for (int j = 0; j < 4; j++) {
            int nn = wn * 32 + j * 8 + (lane & 3) * 2;
            *(float2*)&ep[tl * 136 + nn]       = make_float2(acc[i][j][0], acc[i][j][1]);
            *(float2*)&ep[(tl + 8) * 136 + nn] = make_float2(acc[i][j][2], acc[i][j][3]);
        }
    }
    __syncthreads();
    if (tid < 128) {
        float s = 0.f, q = 0.f;
        for (int t = 0; t < 128; t++) {
            if (t0 + t < TC) {
                float v = ep[t * 136 + tid];
                s += v; q = fmaf(v, v, q);
            }
        }
        atomicAdd(&g_sum[tid], s);
        atomicAdd(&g_sumsq[tid], q);
    }
    float* ybase = g_y + ((size_t)b * 16384 + t0) * 128;
    for (int i = tid; i < 4096; i += 256) {
        int t = i >> 5, c4 = i & 31;
        *(float4*)&ybase[(size_t)t * 128 + c4 * 4] = *(float4*)&ep[t * 136 + c4 * 4];
    }
}

// ---------------------------------------------------------------------------
__global__ void k_stats(const float* __restrict__ g1, const float* __restrict__ b1,
                        const float* __restrict__ g2, const float* __restrict__ b2) {
    int i = threadIdx.x;
    if (i >= 128) return;
    int br = i >> 6, c = i & 63;
    float n = (float)B * (float)TC;
    float mean = g_sum[i] / n;
    float var = g_sumsq[i] / n - mean * mean;
    float gamma = (br == 0) ? g1[c] : g2[c];
    float beta  = (br == 0) ? b1[c] : b2[c];
    float sc = rsqrtf(var + 1e-5f) * gamma;
    g_scale[i] = sc;
    g_shift[i] = beta - mean * sc;
}

// ---------------------------------------------------------------------------
// SPP partial pass over g_y [b][t][n], n-contiguous (coalesced).
__global__ void __launch_bounds__(256) k_spp(const int* __restrict__ orig_len) {
    const int s = blockIdx.x, b = blockIdx.y;
    const int L = orig_len[b] - (KW - 1);
    const int stride = L >> 1, kern = (L + 1) >> 1;
    const int chunk = (L + TSPLIT - 1) / TSPLIT;
    const int tb = s * chunk;
    const int te = min(L, tb + chunk);
    const int n = threadIdx.x & 127, h = threadIdx.x >> 7;
    const float a = g_scale[n], sh = g_shift[n];
    const float* __restrict__ base = g_y + (size_t)b * 16384 * 128 + n;

    __shared__ float r0[256], r1[256], r2[256];
    float e0, e1, e2;
    if (n < 64) {
        float m0 = -INFINITY, m1 = -INFINITY;
        for (int t = tb + h; t < te; t += 2) {
            float v = fmaf(base[(size_t)t * 128], a, sh);
            v = (v > 0.f) ? v : 0.01f * v;
            if (t < kern)    m0 = fmaxf(m0, v);
            if (t >= stride) m1 = fmaxf(m1, v);
        }
        e0 = m0; e1 = m1; e2 = 0.f;
    } else {
        float sa = 0.f, s0 = 0.f, s1 = 0.f;
        for (int t = tb + h; t < te; t += 2) {
            float v = fmaf(base[(size_t)t * 128], a, sh);
            v = (v > 0.f) ? v : 0.01f * v;
            sa += v;
            if (t < kern)    s0 += v;
            if (t >= stride) s1 += v;
        }
        e0 = sa; e1 = s0; e2 = s1;
    }
    r0[threadIdx.x] = e0; r1[threadIdx.x] = e1; r2[threadIdx.x] = e2;
    __syncthreads();
    if (h == 0) {
        int o = threadIdx.x + 128;
        if (n < 64) { e0 = fmaxf(e0, r0[o]); e1 = fmaxf(e1, r1[o]); e2 = 0.f; }
        else        { e0 += r0[o]; e1 += r1[o]; e2 += r2[o]; }
        float* p = g_part + (size_t)(b * TSPLIT + s) * 384;
        p[n] = e0; p[128 + n] = e1; p[256 + n] = e2;
    }
}

__global__ void k_spp2(const int* __restrict__ orig_len) {
    int b = blockIdx.x, n = threadIdx.x;
    if (n >= 128) return;
    int L = orig_len[b] - (KW - 1);
    int kern = (L + 1) >> 1;
    const float* p = g_part + (size_t)b * TSPLIT * 384;
    if (n < 64) {
        float m0 = -INFINITY, m1 = -INFINITY;
        for (int s = 0; s < TSPLIT; s++) {
            m0 = fmaxf(m0, p[s * 384 + n]);
            m1 = fmaxf(m1, p[s * 384 + 128 + n]);
        }
        g_feat[b * 384 + n] = fmaxf(m0, m1);
        g_feat[b * 384 + 64 + 2 * n] = m0;
        g_feat[b * 384 + 65 + 2 * n] = m1;
    } else {
        int c = n - 64;
        float sa = 0.f, s0 = 0.f, s1 = 0.f;
        for (int s = 0; s < TSPLIT; s++) {
            sa += p[s * 384 + n];
            s0 += p[s * 384 + 128 + n];
            s1 += p[s * 384 + 256 + n];
        }
        g_feat[b * 384 + 192 + c] = sa / (float)L;
        g_feat[b * 384 + 256 + 2 * c] = s0 / (float)kern;
        g_feat[b * 384 + 257 + 2 * c] = s1 / (float)kern;
    }
}

// ---------------------------------------------------------------------------
__global__ void k_fc(const float* __restrict__ fc_w, const float* __restrict__ fc_b,
                     float* __restrict__ out) {
    int i = threadIdx.x;
    if (i >= B * 2) return;
    int b = i >> 1, task = i & 1;
    float acc = fc_b[task];
    const float* __restrict__ f = g_feat + b * 384;
    const float* __restrict__ w = fc_w + task * 384;
#pragma unroll 8
    for (int j = 0; j < 384; j++) acc = fmaf(f[j], w[j], acc);
    out[i] = acc;
}

// ---------------------------------------------------------------------------
extern "C" void kernel_launch(void* const* d_in, const int* in_sizes, int n_in,
                              void* d_out, int out_size) {
    const float* x        = (const float*)d_in[0];
    const int*   orig_len = (const int*)  d_in[1];
    const float* w1       = (const float*)d_in[2];
    const float* g1       = (const float*)d_in[3];
    const float* b1       = (const float*)d_in[4];
    const float* w2       = (const float*)d_in[5];
    const float* g2       = (const float*)d_in[6];
    const float* b2       = (const float*)d_in[7];
    const float* fcw      = (const float*)d_in[8];
    const float* fcb      = (const float*)d_in[9];
    float* out = (float*)d_out;

    cudaFuncSetAttribute(k_conv, cudaFuncAttributeMaxDynamicSharedMemorySize,
                         SMEM_TOTAL);

    k_init<<<1, 128>>>();
    k_prepw<<<21, 256>>>(w1, w2);
    dim3 gx(TROWS / 128, B);
    k_prepx<<<gx, 256>>>(x);
    dim3 gc(NTILES, B);
    k_conv<<<gc, 256, SMEM_TOTAL>>>();
    k_stats<<<1, 128>>>(g1, b1, g2, b2);
    dim3 gs(TSPLIT, B);
    k_spp<<<gs, 256>>>(orig_len);
    k_spp2<<<B, 128>>>(orig_len);
    k_fc<<<1, 64>>>(fcw, fcb, out);
}

// round 6
// speedup vs baseline: 6.5690x; 1.5245x over previous
#include <cuda_runtime.h>
#include <cuda_fp16.h>
#include <cstdint>

#define C      64
#define KW     21
#define T_IN   16384
#define TC     (T_IN - KW + 1)   // 16364
#define B      32
#define MT     128
#define NTILES 128               // t tiles
#define TROWS  16512             // padded transposed-x rows (129*128)
#define TSPLIT 8

// smem layout (bytes): xh[21312] wbuf0[18432] wbuf1[18432] ; epilogue needs 69632
#define XS_B    21312            // 148 rows * 144B
#define WB_OFF  21312
#define WB_STR  18432            // 128 rows * 144B
#define SMEM_TOTAL 69632         // max(58176, epilogue 128*136*4)

// ---------------- device scratch (no allocations allowed) -------------------
__device__ uint4 g_wh[21 * 1024];                // W images [k][n=128][ci=64] fp16
__device__ uint4 g_xh[(size_t)B * TROWS * 8];    // X transposed [b][t][ci] fp16
__device__ float g_y[(size_t)B * 16384 * 128];   // conv out [b][t][n]  (268MB)
__device__ float g_sum[128];
__device__ float g_sumsq[128];
__device__ float g_scale[128];
__device__ float g_shift[128];
__device__ float g_part[B * TSPLIT * 3 * 128];
__device__ float g_feat[B * 384];

// ---------------- helpers ----------------------------------------------------
__device__ __forceinline__ uint32_t smem_u32(const void* p) {
    uint32_t a;
    asm("{ .reg .u64 t; cvta.to.shared.u64 t, %1; cvt.u32.u64 %0, t; }" : "=r"(a) : "l"(p));
    return a;
}
__device__ __forceinline__ void cpa16(uint32_t dst, const void* src) {
    asm volatile("cp.async.cg.shared.global [%0], [%1], 16;" :: "r"(dst), "l"(src));
}
#define CP_COMMIT() asm volatile("cp.async.commit_group;" ::: "memory")
#define CP_WAIT0()  asm volatile("cp.async.wait_group 0;" ::: "memory")

__device__ __forceinline__ void ldsm4(uint32_t* r, uint32_t a) {
    asm volatile("ldmatrix.sync.aligned.m8n8.x4.shared.b16 {%0,%1,%2,%3}, [%4];"
                 : "=r"(r[0]), "=r"(r[1]), "=r"(r[2]), "=r"(r[3]) : "r"(a));
}
__device__ __forceinline__ void mma16816(float* d, const uint32_t* a, const uint32_t* b2) {
    asm volatile(
        "mma.sync.aligned.m16n8k16.row.col.f32.f16.f16.f32 "
        "{%0,%1,%2,%3},{%4,%5,%6,%7},{%8,%9},{%0,%1,%2,%3};"
        : "+f"(d[0]), "+f"(d[1]), "+f"(d[2]), "+f"(d[3])
        : "r"(a[0]), "r"(a[1]), "r"(a[2]), "r"(a[3]), "r"(b2[0]), "r"(b2[1]));
}
__device__ __forceinline__ uint32_t pack_h(float a, float b) {
    __half ha = __float2half_rn(a), hb = __float2half_rn(b);
    return (uint32_t)__half_as_ushort(ha) | ((uint32_t)__half_as_ushort(hb) << 16);
}

// ---------------------------------------------------------------------------
__global__ void k_init() {
    int i = threadIdx.x;
    if (i < 128) { g_sum[i] = 0.f; g_sumsq[i] = 0.f; }
}

// W images: [k][n][ci] fp16 rows of 128B (n<64: w1, else w2)
__global__ void k_prepw(const float* __restrict__ w1, const float* __restrict__ w2) {
    int k = blockIdx.x;
    uint32_t* dh = (uint32_t*)g_wh;
    for (int idx = threadIdx.x; idx < 128 * 32; idx += 256) {
        int n = idx >> 5, p = idx & 31, ci = 2 * p;
        const float* src = (n < 64) ? (w1 + ((size_t)n * C + ci) * KW + k)
                                    : (w2 + ((size_t)(n - 64) * C + ci) * KW + k);
        dh[(k * 128 + n) * 32 + p] = pack_h(src[0], src[KW]);
    }
}

// X transpose -> [b][t][ci] fp16
__global__ void __launch_bounds__(256) k_prepx(const float* __restrict__ x) {
    __shared__ float smx[64][129];
    int b = blockIdx.y, t0 = blockIdx.x * 128;
    for (int idx = threadIdx.x; idx < 64 * 128; idx += 256) {
        int ci = idx >> 7, tt = idx & 127;
        int t = t0 + tt;
        smx[ci][tt] = (t < T_IN) ? x[((size_t)b * C + ci) * T_IN + t] : 0.f;
    }
    __syncthreads();
    uint32_t* dh = (uint32_t*)g_xh;
    for (int idx = threadIdx.x; idx < 128 * 32; idx += 256) {
        int tt = idx >> 5, p = idx & 31;
        size_t gi = ((size_t)b * TROWS + t0 + tt) * 32 + p;
        dh[gi] = pack_h(smx[2 * p][tt], smx[2 * p + 1][tt]);
    }
}

// ---------------------------------------------------------------------------
__device__ __forceinline__ void stage_w(uint32_t wb_u, int k, int buf, int tid) {
    const uint4* sh = g_wh + (size_t)k * 1024;
    uint32_t base = wb_u + buf * WB_STR;
    for (int i = tid; i < 1024; i += 256) {
        int r = i >> 3, c2 = i & 7;
        cpa16(base + r * 144 + c2 * 16, sh + i);
    }
}

// Main mma.sync conv: block (tile, b), 256 threads = 8 warps (2m x 4n),
// warp tile 64x32, D[t=128][n=128] in registers. Single fp16 product.
__global__ void __launch_bounds__(256, 2) k_conv() {
    extern __shared__ __align__(1024) char sm[];
    const int tile = blockIdx.x, b = blockIdx.y;
    const int t0 = tile * MT;
    const int tid = threadIdx.x;
    const int wid = tid >> 5, lane = tid & 31;
    const int wm = wid & 1, wn = wid >> 1;

    const uint32_t sm_u = smem_u32(sm);
    const uint32_t xs_h = sm_u;
    const uint32_t wb_u = sm_u + WB_OFF;

    // stage X tile (148 rows) + W k=0 via cp.async
    {
        const uint4* sxh = g_xh + ((size_t)b * TROWS + t0) * 8;
        for (int i = tid; i < 1184; i += 256) {
            int r = i >> 3, c2 = i & 7;
            cpa16(xs_h + r * 144 + c2 * 16, sxh + i);
        }
        stage_w(wb_u, 0, 0, tid);
        CP_COMMIT();
    }

    // per-warp ldmatrix base addresses
    uint32_t cA[4];
#pragma unroll
    for (int i = 0; i < 4; i++)
        cA[i] = (uint32_t)((wm * 64 + i * 16 + (lane & 15)) * 144 + ((lane >> 4) * 16));
    uint32_t cB[2];
#pragma unroll
    for (int p = 0; p < 2; p++)
        cB[p] = (uint32_t)((wn * 32 + p * 16 + ((lane >> 4) << 3) + (lane & 7)) * 144 +
                           (((lane >> 3) & 1) * 16));

    float acc[4][4][4];
#pragma unroll
    for (int i = 0; i < 4; i++)
#pragma unroll
        for (int j = 0; j < 4; j++)
#pragma unroll
            for (int e = 0; e < 4; e++) acc[i][j][e] = 0.f;

    CP_WAIT0();
    __syncthreads();

#pragma unroll 1
    for (int k = 0; k < KW; k++) {
        const int buf = k & 1;
        if (k + 1 < KW) { stage_w(wb_u, k + 1, buf ^ 1, tid); CP_COMMIT(); }

        const uint32_t axh = xs_h + k * 144;
        const uint32_t bwh = wb_u + buf * WB_STR;

#pragma unroll
        for (int ks = 0; ks < 4; ks++) {
            uint32_t ah[4][4], bh[2][4];
#pragma unroll
            for (int i = 0; i < 4; i++) ldsm4(ah[i], axh + cA[i] + ks * 32);
#pragma unroll
            for (int p = 0; p < 2; p++) ldsm4(bh[p], bwh + cB[p] + ks * 32);
#pragma unroll
            for (int i = 0; i < 4; i++)
#pragma unroll
                for (int j = 0; j < 4; j++)
                    mma16816(acc[i][j], ah[i], &bh[j >> 1][(j & 1) * 2]);
        }
        if (k + 1 < KW) CP_WAIT0();
        __syncthreads();
    }

    // Epilogue: acc -> smem [t][n] (stride 136 floats; aliases X+W regions),
    // BN partial sums, coalesced STG of y.
    float* ep = (float*)sm;
#pragma unroll
    for (int i = 0; i < 4; i++) {
        int tl = wm * 64 + i * 16 + (lane >> 2);
#pragma unroll
        for (int j = 0; j < 4; j++) {
            int nn = wn * 32 + j * 8 + (lane & 3) * 2;
            *(float2*)&ep[tl * 136 + nn]       = make_float2(acc[i][j][0], acc[i][j][1]);
            *(float2*)&ep[(tl + 8) * 136 + nn] = make_float2(acc[i][j][2], acc[i][j][3]);
        }
    }
    __syncthreads();
    if (tid < 128) {
        float s = 0.f, q = 0.f;
        for (int t = 0; t < 128; t++) {
            if (t0 + t < TC) {
                float v = ep[t * 136 + tid];
                s += v; q = fmaf(v, v, q);
            }
        }
        atomicAdd(&g_sum[tid], s);
        atomicAdd(&g_sumsq[tid], q);
    }
    float* ybase = g_y + ((size_t)b * 16384 + t0) * 128;
    for (int i = tid; i < 4096; i += 256) {
        int t = i >> 5, c4 = i & 31;
        *(float4*)&ybase[(size_t)t * 128 + c4 * 4] = *(float4*)&ep[t * 136 + c4 * 4];
    }
}

// ---------------------------------------------------------------------------
__global__ void k_stats(const float* __restrict__ g1, const float* __restrict__ b1,
                        const float* __restrict__ g2, const float* __restrict__ b2) {
    int i = threadIdx.x;
    if (i >= 128) return;
    int br = i >> 6, c = i & 63;
    float n = (float)B * (float)TC;
    float mean = g_sum[i] / n;
    float var = g_sumsq[i] / n - mean * mean;
    float gamma = (br == 0) ? g1[c] : g2[c];
    float beta  = (br == 0) ? b1[c] : b2[c];
    float sc = rsqrtf(var + 1e-5f) * gamma;
    g_scale[i] = sc;
    g_shift[i] = beta - mean * sc;
}

// ---------------------------------------------------------------------------
// SPP partial pass over g_y [b][t][n], n-contiguous (coalesced).
__global__ void __launch_bounds__(256) k_spp(const int* __restrict__ orig_len) {
    const int s = blockIdx.x, b = blockIdx.y;
    const int L = orig_len[b] - (KW - 1);
    const int stride = L >> 1, kern = (L + 1) >> 1;
    const int chunk = (L + TSPLIT - 1) / TSPLIT;
    const int tb = s * chunk;
    const int te = min(L, tb + chunk);
    const int n = threadIdx.x & 127, h = threadIdx.x >> 7;
    const float a = g_scale[n], sh = g_shift[n];
    const float* __restrict__ base = g_y + (size_t)b * 16384 * 128 + n;

    __shared__ float r0[256], r1[256], r2[256];
    float e0, e1, e2;
    if (n < 64) {
        float m0 = -INFINITY, m1 = -INFINITY;
        for (int t = tb + h; t < te; t += 2) {
            float v = fmaf(base[(size_t)t * 128], a, sh);
            v = (v > 0.f) ? v : 0.01f * v;
            if (t < kern)    m0 = fmaxf(m0, v);
            if (t >= stride) m1 = fmaxf(m1, v);
        }
        e0 = m0; e1 = m1; e2 = 0.f;
    } else {
        float sa = 0.f, s0 = 0.f, s1 = 0.f;
        for (int t = tb + h; t < te; t += 2) {
            float v = fmaf(base[(size_t)t * 128], a, sh);
            v = (v > 0.f) ? v : 0.01f * v;
            sa += v;
            if (t < kern)    s0 += v;
            if (t >= stride) s1 += v;
        }
        e0 = sa; e1 = s0; e2 = s1;
    }
    r0[threadIdx.x] = e0; r1[threadIdx.x] = e1; r2[threadIdx.x] = e2;
    __syncthreads();
    if (h == 0) {
        int o = threadIdx.x + 128;
        if (n < 64) { e0 = fmaxf(e0, r0[o]); e1 = fmaxf(e1, r1[o]); e2 = 0.f; }
        else        { e0 += r0[o]; e1 += r1[o]; e2 += r2[o]; }
        float* p = g_part + (size_t)(b * TSPLIT + s) * 384;
        p[n] = e0; p[128 + n] = e1; p[256 + n] = e2;
    }
}

__global__ void k_spp2(const int* __restrict__ orig_len) {
    int b = blockIdx.x, n = threadIdx.x;
    if (n >= 128) return;
    int L = orig_len[b] - (KW - 1);
    int kern = (L + 1) >> 1;
    const float* p = g_part + (size_t)b * TSPLIT * 384;
    if (n < 64) {
        float m0 = -INFINITY, m1 = -INFINITY;
        for (int s = 0; s < TSPLIT; s++) {
            m0 = fmaxf(m0, p[s * 384 + n]);
            m1 = fmaxf(m1, p[s * 384 + 128 + n]);
        }
        g_feat[b * 384 + n] = fmaxf(m0, m1);
        g_feat[b * 384 + 64 + 2 * n] = m0;
        g_feat[b * 384 + 65 + 2 * n] = m1;
    } else {
        int c = n - 64;
        float sa = 0.f, s0 = 0.f, s1 = 0.f;
        for (int s = 0; s < TSPLIT; s++) {
            sa += p[s * 384 + n];
            s0 += p[s * 384 + 128 + n];
            s1 += p[s * 384 + 256 + n];
        }
        g_feat[b * 384 + 192 + c] = sa / (float)L;
        g_feat[b * 384 + 256 + 2 * c] = s0 / (float)kern;
        g_feat[b * 384 + 257 + 2 * c] = s1 / (float)kern;
    }
}

// ---------------------------------------------------------------------------
__global__ void k_fc(const float* __restrict__ fc_w, const float* __restrict__ fc_b,
                     float* __restrict__ out) {
    int i = threadIdx.x;
    if (i >= B * 2) return;
    int b = i >> 1, task = i & 1;
    float acc = fc_b[task];
    const float* __restrict__ f = g_feat + b * 384;
    const float* __restrict__ w = fc_w + task * 384;
#pragma unroll 8
    for (int j = 0; j < 384; j++) acc = fmaf(f[j], w[j], acc);
    out[i] = acc;
}

// ---------------------------------------------------------------------------
extern "C" void kernel_launch(void* const* d_in, const int* in_sizes, int n_in,
                              void* d_out, int out_size) {
    const float* x        = (const float*)d_in[0];
    const int*   orig_len = (const int*)  d_in[1];
    const float* w1       = (const float*)d_in[2];
    const float* g1       = (const float*)d_in[3];
    const float* b1       = (const float*)d_in[4];
    const float* w2       = (const float*)d_in[5];
    const float* g2       = (const float*)d_in[6];
    const float* b2       = (const float*)d_in[7];
    const float* fcw      = (const float*)d_in[8];
    const float* fcb      = (const float*)d_in[9];
    float* out = (float*)d_out;

    cudaFuncSetAttribute(k_conv, cudaFuncAttributeMaxDynamicSharedMemorySize,
                         SMEM_TOTAL);

    k_init<<<1, 128>>>();
    k_prepw<<<21, 256>>>(w1, w2);
    dim3 gx(TROWS / 128, B);
    k_prepx<<<gx, 256>>>(x);
    dim3 gc(NTILES, B);
    k_conv<<<gc, 256, SMEM_TOTAL>>>();
    k_stats<<<1, 128>>>(g1, b1, g2, b2);
    dim3 gs(TSPLIT, B);
    k_spp<<<gs, 256>>>(orig_len);
    k_spp2<<<B, 128>>>(orig_len);
    k_fc<<<1, 64>>>(fcw, fcb, out);
}

// round 7
// speedup vs baseline: 7.2244x; 1.0998x over previous
#include <cuda_runtime.h>
#include <cuda_fp16.h>
#include <cstdint>

#define C      64
#define KW     21
#define T_IN   16384
#define TC     (T_IN - KW + 1)   // 16364
#define B      32
#define MT     128
#define NTILES 128
#define TROWS  16512             // padded transposed-x rows (129*128)
#define TSPLIT 8

// smem (bytes): xh[21312] wpair0[36864] wpair1[36864]
#define XS_B     21312           // 148 rows * 144B
#define WB_OFF   21312
#define WSLOT    18432           // one k: 128 rows * 144B
#define WPAIR    36864
#define SMEM_TOTAL 95040

// ---------------- device scratch (no allocations allowed) -------------------
__device__ uint4  g_wh[21 * 1024];               // W images [k][n=128][ci=64] fp16
__device__ uint4  g_xh[(size_t)B * TROWS * 8];   // X transposed [b][t][ci] fp16
__device__ __half g_yh[(size_t)B * 16384 * 128]; // conv out [b][t][n] fp16 (134MB)
__device__ float  g_sum[128];
__device__ float  g_sumsq[128];
__device__ float  g_scale[128];
__device__ float  g_shift[128];
__device__ float  g_part[B * TSPLIT * 3 * 128];

// ---------------- helpers ----------------------------------------------------
__device__ __forceinline__ uint32_t smem_u32(const void* p) {
    uint32_t a;
    asm("{ .reg .u64 t; cvta.to.shared.u64 t, %1; cvt.u32.u64 %0, t; }" : "=r"(a) : "l"(p));
    return a;
}
__device__ __forceinline__ void cpa16(uint32_t dst, const void* src) {
    asm volatile("cp.async.cg.shared.global [%0], [%1], 16;" :: "r"(dst), "l"(src));
}
#define CP_COMMIT() asm volatile("cp.async.commit_group;" ::: "memory")
#define CP_WAIT0()  asm volatile("cp.async.wait_group 0;" ::: "memory")

__device__ __forceinline__ void ldsm4(uint32_t* r, uint32_t a) {
    asm volatile("ldmatrix.sync.aligned.m8n8.x4.shared.b16 {%0,%1,%2,%3}, [%4];"
                 : "=r"(r[0]), "=r"(r[1]), "=r"(r[2]), "=r"(r[3]) : "r"(a));
}
__device__ __forceinline__ void mma16816(float* d, const uint32_t* a, const uint32_t* b2) {
    asm volatile(
        "mma.sync.aligned.m16n8k16.row.col.f32.f16.f16.f32 "
        "{%0,%1,%2,%3},{%4,%5,%6,%7},{%8,%9},{%0,%1,%2,%3};"
        : "+f"(d[0]), "+f"(d[1]), "+f"(d[2]), "+f"(d[3])
        : "r"(a[0]), "r"(a[1]), "r"(a[2]), "r"(a[3]), "r"(b2[0]), "r"(b2[1]));
}
__device__ __forceinline__ uint32_t pack_h(float a, float b) {
    __half ha = __float2half_rn(a), hb = __float2half_rn(b);
    return (uint32_t)__half_as_ushort(ha) | ((uint32_t)__half_as_ushort(hb) << 16);
}

// ---------------------------------------------------------------------------
__global__ void k_init() {
    int i = threadIdx.x;
    if (i < 128) { g_sum[i] = 0.f; g_sumsq[i] = 0.f; }
}

// W images: [k][n][ci] fp16 rows of 128B (n<64: w1, else w2)
__global__ void k_prepw(const float* __restrict__ w1, const float* __restrict__ w2) {
    int k = blockIdx.x;
    uint32_t* dh = (uint32_t*)g_wh;
    for (int idx = threadIdx.x; idx < 128 * 32; idx += 256) {
        int n = idx >> 5, p = idx & 31, ci = 2 * p;
        const float* src = (n < 64) ? (w1 + ((size_t)n * C + ci) * KW + k)
                                    : (w2 + ((size_t)(n - 64) * C + ci) * KW + k);
        dh[(k * 128 + n) * 32 + p] = pack_h(src[0], src[KW]);
    }
}

// X transpose -> [b][t][ci] fp16
__global__ void __launch_bounds__(256) k_prepx(const float* __restrict__ x) {
    __shared__ float smx[64][129];
    int b = blockIdx.y, t0 = blockIdx.x * 128;
    for (int idx = threadIdx.x; idx < 64 * 128; idx += 256) {
        int ci = idx >> 7, tt = idx & 127;
        int t = t0 + tt;
        smx[ci][tt] = (t < T_IN) ? x[((size_t)b * C + ci) * T_IN + t] : 0.f;
    }
    __syncthreads();
    uint32_t* dh = (uint32_t*)g_xh;
    for (int idx = threadIdx.x; idx < 128 * 32; idx += 256) {
        int tt = idx >> 5, p = idx & 31;
        size_t gi = ((size_t)b * TROWS + t0 + tt) * 32 + p;
        dh[gi] = pack_h(smx[2 * p][tt], smx[2 * p + 1][tt]);
    }
}

// ---------------------------------------------------------------------------
__device__ __forceinline__ void stage_w(uint32_t dst, int k, int tid) {
    const uint4* sh = g_wh + (size_t)k * 1024;
    for (int i = tid; i < 1024; i += 256) {
        int r = i >> 3, c2 = i & 7;
        cpa16(dst + r * 144 + c2 * 16, sh + i);
    }
}

// Main mma.sync conv: block (tile, b), 256 threads = 8 warps (2m x 4n),
// warp tile 64x32, D[t=128][n=128] in registers. 2 k per mainloop iteration.
__global__ void __launch_bounds__(256, 2) k_conv() {
    extern __shared__ __align__(1024) char sm[];
    const int tile = blockIdx.x, b = blockIdx.y;
    const int t0 = tile * MT;
    const int tid = threadIdx.x;
    const int wid = tid >> 5, lane = tid & 31;
    const int wm = wid & 1, wn = wid >> 1;

    const uint32_t sm_u = smem_u32(sm);
    const uint32_t xs_h = sm_u;
    const uint32_t wb_u = sm_u + WB_OFF;

    // stage X tile (148 rows) + W[0], W[1] into pair-buffer 0
    {
        const uint4* sxh = g_xh + ((size_t)b * TROWS + t0) * 8;
        for (int i = tid; i < 1184; i += 256) {
            int r = i >> 3, c2 = i & 7;
            cpa16(xs_h + r * 144 + c2 * 16, sxh + i);
        }
        stage_w(wb_u, 0, tid);
        stage_w(wb_u + WSLOT, 1, tid);
        CP_COMMIT();
    }

    // per-warp ldmatrix base addresses
    uint32_t cA[4];
#pragma unroll
    for (int i = 0; i < 4; i++)
        cA[i] = (uint32_t)((wm * 64 + i * 16 + (lane & 15)) * 144 + ((lane >> 4) * 16));
    uint32_t cB[2];
#pragma unroll
    for (int p = 0; p < 2; p++)
        cB[p] = (uint32_t)((wn * 32 + p * 16 + ((lane >> 4) << 3) + (lane & 7)) * 144 +
                           (((lane >> 3) & 1) * 16));

    float acc[4][4][4];
#pragma unroll
    for (int i = 0; i < 4; i++)
#pragma unroll
        for (int j = 0; j < 4; j++)
#pragma unroll
            for (int e = 0; e < 4; e++) acc[i][j][e] = 0.f;

    CP_WAIT0();
    __syncthreads();

#pragma unroll 1
    for (int kk = 0; kk < KW; kk += 2) {
        const int buf = (kk >> 1) & 1;
        const uint32_t base = wb_u + buf * WPAIR;
        if (kk + 2 < KW) {
            const uint32_t nb = wb_u + (buf ^ 1) * WPAIR;
            stage_w(nb, kk + 2, tid);
            if (kk + 3 < KW) stage_w(nb + WSLOT, kk + 3, tid);
            CP_COMMIT();
        }
#pragma unroll 1
        for (int kq = 0; kq < 2; kq++) {
            const int k = kk + kq;
            if (k >= KW) break;
            const uint32_t axh = xs_h + k * 144;
            const uint32_t bwh = base + kq * WSLOT;
#pragma unroll
            for (int ks = 0; ks < 4; ks++) {
                uint32_t ah[4][4], bh[2][4];
#pragma unroll
                for (int i = 0; i < 4; i++) ldsm4(ah[i], axh + cA[i] + ks * 32);
#pragma unroll
                for (int p = 0; p < 2; p++) ldsm4(bh[p], bwh + cB[p] + ks * 32);
#pragma unroll
                for (int i = 0; i < 4; i++)
#pragma unroll
                    for (int j = 0; j < 4; j++)
                        mma16816(acc[i][j], ah[i], &bh[j >> 1][(j & 1) * 2]);
            }
        }
        CP_WAIT0();
        __syncthreads();
    }

    // Epilogue: acc -> smem [t][n] (stride 136 floats; aliases X+W regions),
    // BN partial sums, coalesced fp16 STG of y.
    float* ep = (float*)sm;
#pragma unroll
    for (int i = 0; i < 4; i++) {
        int tl = wm * 64 + i * 16 + (lane >> 2);
#pragma unroll
        for (int j = 0; j < 4; j++) {
            int nn = wn * 32 + j * 8 + (lane & 3) * 2;
            *(float2*)&ep[tl * 136 + nn]       = make_float2(acc[i][j][0], acc[i][j][1]);
            *(float2*)&ep[(tl + 8) * 136 + nn] = make_float2(acc[i][j][2], acc[i][j][3]);
        }
    }
    __syncthreads();
    if (tid < 128) {
        float s = 0.f, q = 0.f;
        for (int t = 0; t < 128; t++) {
            if (t0 + t < TC) {
                float v = ep[t * 136 + tid];
                s += v; q = fmaf(v, v, q);
            }
        }
        atomicAdd(&g_sum[tid], s);
        atomicAdd(&g_sumsq[tid], q);
    }
    __half* ybase = g_yh + ((size_t)b * 16384 + t0) * 128;
    for (int i = tid; i < 4096; i += 256) {
        int t = i >> 5, c4 = i & 31;
        float4 v = *(float4*)&ep[t * 136 + c4 * 4];
        __half2 h0 = __floats2half2_rn(v.x, v.y);
        __half2 h1 = __floats2half2_rn(v.z, v.w);
        uint2 u;
        u.x = *(uint32_t*)&h0;
        u.y = *(uint32_t*)&h1;
        *(uint2*)(ybase + (size_t)t * 128 + c4 * 4) = u;
    }
}

// ---------------------------------------------------------------------------
__global__ void k_stats(const float* __restrict__ g1, const float* __restrict__ b1,
                        const float* __restrict__ g2, const float* __restrict__ b2) {
    int i = threadIdx.x;
    if (i >= 128) return;
    int br = i >> 6, c = i & 63;
    float n = (float)B * (float)TC;
    float mean = g_sum[i] / n;
    float var = g_sumsq[i] / n - mean * mean;
    float gamma = (br == 0) ? g1[c] : g2[c];
    float beta  = (br == 0) ? b1[c] : b2[c];
    float sc = rsqrtf(var + 1e-5f) * gamma;
    g_scale[i] = sc;
    g_shift[i] = beta - mean * sc;
}

// ---------------------------------------------------------------------------
// SPP partial pass over fp16 y [b][t][n]; each thread owns channel pair (2p,2p+1).
__global__ void __launch_bounds__(256) k_spp(const int* __restrict__ orig_len) {
    const int s = blockIdx.x, b = blockIdx.y;
    const int L = orig_len[b] - (KW - 1);
    const int stride = L >> 1, kern = (L + 1) >> 1;
    const int chunk = (L + TSPLIT - 1) / TSPLIT;
    const int tb = s * chunk;
    const int te = min(L, tb + chunk);
    const int p = threadIdx.x & 63, h = threadIdx.x >> 6;   // 4-way t split
    const int c0 = 2 * p, c1 = 2 * p + 1;
    const float ax = g_scale[c0], ay = g_scale[c1];
    const float sx = g_shift[c0], sy = g_shift[c1];
    const __half2* __restrict__ base =
        (const __half2*)g_yh + (size_t)b * 16384 * 64 + p;

    __shared__ float2 r0[256], r1[256], r2[256];
    float2 e0, e1, e2;
    if (p < 32) {
        float2 m0 = make_float2(-INFINITY, -INFINITY);
        float2 m1 = make_float2(-INFINITY, -INFINITY);
        for (int t = tb + h; t < te; t += 4) {
            float2 v = __half22float2(base[(size_t)t * 64]);
            v.x = fmaf(v.x, ax, sx); v.y = fmaf(v.y, ay, sy);
            v.x = (v.x > 0.f) ? v.x : 0.01f * v.x;
            v.y = (v.y > 0.f) ? v.y : 0.01f * v.y;
            if (t < kern)    { m0.x = fmaxf(m0.x, v.x); m0.y = fmaxf(m0.y, v.y); }
            if (t >= stride) { m1.x = fmaxf(m1.x, v.x); m1.y = fmaxf(m1.y, v.y); }
        }
        e0 = m0; e1 = m1; e2 = make_float2(0.f, 0.f);
    } else {
        float2 sa = make_float2(0.f, 0.f), s0 = sa, s1 = sa;
        for (int t = tb + h; t < te; t += 4) {
            float2 v = __half22float2(base[(size_t)t * 64]);
            v.x = fmaf(v.x, ax, sx); v.y = fmaf(v.y, ay, sy);
            v.x = (v.x > 0.f) ? v.x : 0.01f * v.x;
            v.y = (v.y > 0.f) ? v.y : 0.01f * v.y;
            sa.x += v.x; sa.y += v.y;
            if (t < kern)    { s0.x += v.x; s0.y += v.y; }
            if (t >= stride) { s1.x += v.x; s1.y += v.y; }
        }
        e0 = sa; e1 = s0; e2 = s1;
    }
    r0[threadIdx.x] = e0; r1[threadIdx.x] = e1; r2[threadIdx.x] = e2;
    __syncthreads();
    if (h == 0) {
#pragma unroll
        for (int g = 1; g < 4; g++) {
            int o = threadIdx.x + g * 64;
            if (p < 32) {
                e0.x = fmaxf(e0.x, r0[o].x); e0.y = fmaxf(e0.y, r0[o].y);
                e1.x = fmaxf(e1.x, r1[o].x); e1.y = fmaxf(e1.y, r1[o].y);
            } else {
                e0.x += r0[o].x; e0.y += r0[o].y;
                e1.x += r1[o].x; e1.y += r1[o].y;
                e2.x += r2[o].x; e2.y += r2[o].y;
            }
        }
        float* pp = g_part + (size_t)(b * TSPLIT + s) * 384;
        pp[c0] = e0.x;       pp[c1] = e0.y;
        pp[128 + c0] = e1.x; pp[128 + c1] = e1.y;
        pp[256 + c0] = e2.x; pp[256 + c1] = e2.y;
    }
}

// Combine partials -> features -> FC output, one block per b.
__global__ void k_spp2fc(const int* __restrict__ orig_len,
                         const float* __restrict__ fc_w,
                         const float* __restrict__ fc_b,
                         float* __restrict__ out) {
    int b = blockIdx.x, n = threadIdx.x;
    __shared__ float feat[384];
    int L = orig_len[b] - (KW - 1);
    int kern = (L + 1) >> 1;
    const float* p = g_part + (size_t)b * TSPLIT * 384;
    if (n < 128) {
        if (n < 64) {
            float m0 = -INFINITY, m1 = -INFINITY;
            for (int s = 0; s < TSPLIT; s++) {
                m0 = fmaxf(m0, p[s * 384 + n]);
                m1 = fmaxf(m1, p[s * 384 + 128 + n]);
            }
            feat[n] = fmaxf(m0, m1);
            feat[64 + 2 * n] = m0;
            feat[65 + 2 * n] = m1;
        } else {
            int c = n - 64;
            float sa = 0.f, s0 = 0.f, s1 = 0.f;
            for (int s = 0; s < TSPLIT; s++) {
                sa += p[s * 384 + n];
                s0 += p[s * 384 + 128 + n];
                s1 += p[s * 384 + 256 + n];
            }
            feat[192 + c] = sa / (float)L;
            feat[256 + 2 * c] = s0 / (float)kern;
            feat[257 + 2 * c] = s1 / (float)kern;
        }
    }
    __syncthreads();
    if (n < 64) {
        int task = n >> 5, lane = n & 31;
        float acc = 0.f;
        for (int j = lane; j < 384; j += 32)
            acc = fmaf(feat[j], fc_w[task * 384 + j], acc);
#pragma unroll
        for (int off = 16; off; off >>= 1)
            acc += __shfl_down_sync(0xffffffffu, acc, off);
        if (lane == 0) out[b * 2 + task] = acc + fc_b[task];
    }
}

// ---------------------------------------------------------------------------
extern "C" void kernel_launch(void* const* d_in, const int* in_sizes, int n_in,
                              void* d_out, int out_size) {
    const float* x        = (const float*)d_in[0];
    const int*   orig_len = (const int*)  d_in[1];
    const float* w1       = (const float*)d_in[2];
    const float* g1       = (const float*)d_in[3];
    const float* b1       = (const float*)d_in[4];
    const float* w2       = (const float*)d_in[5];
    const float* g2       = (const float*)d_in[6];
    const float* b2       = (const float*)d_in[7];
    const float* fcw      = (const float*)d_in[8];
    const float* fcb      = (const float*)d_in[9];
    float* out = (float*)d_out;

    cudaFuncSetAttribute(k_conv, cudaFuncAttributeMaxDynamicSharedMemorySize,
                         SMEM_TOTAL);

    k_init<<<1, 128>>>();
    k_prepw<<<21, 256>>>(w1, w2);
    dim3 gx(TROWS / 128, B);
    k_prepx<<<gx, 256>>>(x);
    dim3 gc(NTILES, B);
    k_conv<<<gc, 256, SMEM_TOTAL>>>();
    k_stats<<<1, 128>>>(g1, b1, g2, b2);
    dim3 gs(TSPLIT, B);
    k_spp<<<gs, 256>>>(orig_len);
    k_spp2fc<<<B, 128>>>(orig_len, fcw, fcb, out);
}

// round 8
// speedup vs baseline: 7.3714x; 1.0204x over previous
#include <cuda_runtime.h>
#include <cuda_fp16.h>
#include <cstdint>

#define C      64
#define KW     21
#define T_IN   16384
#define TC     (T_IN - KW + 1)   // 16364
#define B      32
#define MT     128
#define NTILES 128
#define TROWS  16512             // padded transposed-x rows (129*128)
#define TSPLIT 8

// smem (bytes): xh[21312] wpair0[36864] wpair1[36864]; epilogue aliases 69632
#define XS_B     21312
#define WB_OFF   21312
#define WSLOT    18432
#define WPAIR    36864
#define SMEM_TOTAL 95040

// ---------------- device scratch (no allocations allowed) -------------------
__device__ uint4    g_wh[21 * 1024];               // W images [k][n=128][ci=64] fp16
__device__ uint4    g_xh[(size_t)B * TROWS * 8];   // X transposed [b][t][ci] fp16
__device__ __half   g_y2[(size_t)B * 16384 * 64];  // avg-branch y [b][t][c] fp16 (67MB)
__device__ float    g_sum[128];
__device__ float    g_sumsq[128];
__device__ float    g_scale[128];
__device__ float    g_shift[128];
__device__ unsigned g_mm[B * 64 * 4];              // enc(max), enc(-min) per bin0/bin1
__device__ float    g_part[B * TSPLIT * 192];

// ---------------- helpers ----------------------------------------------------
__device__ __forceinline__ uint32_t smem_u32(const void* p) {
    uint32_t a;
    asm("{ .reg .u64 t; cvta.to.shared.u64 t, %1; cvt.u32.u64 %0, t; }" : "=r"(a) : "l"(p));
    return a;
}
__device__ __forceinline__ void cpa16(uint32_t dst, const void* src) {
    asm volatile("cp.async.cg.shared.global [%0], [%1], 16;" :: "r"(dst), "l"(src));
}
#define CP_COMMIT() asm volatile("cp.async.commit_group;" ::: "memory")
#define CP_WAIT0()  asm volatile("cp.async.wait_group 0;" ::: "memory")

__device__ __forceinline__ void ldsm4(uint32_t* r, uint32_t a) {
    asm volatile("ldmatrix.sync.aligned.m8n8.x4.shared.b16 {%0,%1,%2,%3}, [%4];"
                 : "=r"(r[0]), "=r"(r[1]), "=r"(r[2]), "=r"(r[3]) : "r"(a));
}
__device__ __forceinline__ void mma16816(float* d, const uint32_t* a, const uint32_t* b2) {
    asm volatile(
        "mma.sync.aligned.m16n8k16.row.col.f32.f16.f16.f32 "
        "{%0,%1,%2,%3},{%4,%5,%6,%7},{%8,%9},{%0,%1,%2,%3};"
        : "+f"(d[0]), "+f"(d[1]), "+f"(d[2]), "+f"(d[3])
        : "r"(a[0]), "r"(a[1]), "r"(a[2]), "r"(a[3]), "r"(b2[0]), "r"(b2[1]));
}
__device__ __forceinline__ uint32_t pack_h(float a, float b) {
    __half ha = __float2half_rn(a), hb = __float2half_rn(b);
    return (uint32_t)__half_as_ushort(ha) | ((uint32_t)__half_as_ushort(hb) << 16);
}
// monotone float <-> uint encoding for atomicMax-based float max
__device__ __forceinline__ uint32_t fenc(float f) {
    uint32_t u = __float_as_uint(f);
    return (u & 0x80000000u) ? ~u : (u | 0x80000000u);
}
__device__ __forceinline__ float fdec(uint32_t u) {
    return __uint_as_float((u & 0x80000000u) ? (u ^ 0x80000000u) : ~u);
}

// ---------------------------------------------------------------------------
__global__ void k_init() {
    int i = threadIdx.x;
    if (i < 128) { g_sum[i] = 0.f; g_sumsq[i] = 0.f; }
    const uint32_t NEGINF = 0x007FFFFFu;   // fenc(-inf)
    for (int j = i; j < B * 64 * 4; j += 128) g_mm[j] = NEGINF;
}

// W images: [k][n][ci] fp16 rows of 128B (n<64: w1, else w2)
__global__ void k_prepw(const float* __restrict__ w1, const float* __restrict__ w2) {
    int k = blockIdx.x;
    uint32_t* dh = (uint32_t*)g_wh;
    for (int idx = threadIdx.x; idx < 128 * 32; idx += 256) {
        int n = idx >> 5, p = idx & 31, ci = 2 * p;
        const float* src = (n < 64) ? (w1 + ((size_t)n * C + ci) * KW + k)
                                    : (w2 + ((size_t)(n - 64) * C + ci) * KW + k);
        dh[(k * 128 + n) * 32 + p] = pack_h(src[0], src[KW]);
    }
}

// X transpose -> [b][t][ci] fp16
__global__ void __launch_bounds__(256) k_prepx(const float* __restrict__ x) {
    __shared__ float smx[64][129];
    int b = blockIdx.y, t0 = blockIdx.x * 128;
    for (int idx = threadIdx.x; idx < 64 * 128; idx += 256) {
        int ci = idx >> 7, tt = idx & 127;
        int t = t0 + tt;
        smx[ci][tt] = (t < T_IN) ? x[((size_t)b * C + ci) * T_IN + t] : 0.f;
    }
    __syncthreads();
    uint32_t* dh = (uint32_t*)g_xh;
    for (int idx = threadIdx.x; idx < 128 * 32; idx += 256) {
        int tt = idx >> 5, p = idx & 31;
        size_t gi = ((size_t)b * TROWS + t0 + tt) * 32 + p;
        dh[gi] = pack_h(smx[2 * p][tt], smx[2 * p + 1][tt]);
    }
}

// ---------------------------------------------------------------------------
__device__ __forceinline__ void stage_w(uint32_t dst, int k, int tid) {
    const uint4* sh = g_wh + (size_t)k * 1024;
    for (int i = tid; i < 1024; i += 256) {
        int r = i >> 3, c2 = i & 7;
        cpa16(dst + r * 144 + c2 * 16, sh + i);
    }
}

// Main mma.sync conv: block (tile, b), 256 threads = 8 warps (2m x 4n),
// warp tile 64x32, D[t=128][n=128] in registers. 2 k per mainloop iteration.
// Epilogue: BN partial sums for all n; fused max-pool bins for n<64 (exact,
// via raw max/min + ordered-uint atomics); fp16 store of avg-branch y only.
__global__ void __launch_bounds__(256, 2) k_conv(const int* __restrict__ orig_len) {
    extern __shared__ __align__(1024) char sm[];
    const int tile = blockIdx.x, b = blockIdx.y;
    const int t0 = tile * MT;
    const int tid = threadIdx.x;
    const int wid = tid >> 5, lane = tid & 31;
    const int wm = wid & 1, wn = wid >> 1;

    const uint32_t sm_u = smem_u32(sm);
    const uint32_t xs_h = sm_u;
    const uint32_t wb_u = sm_u + WB_OFF;

    // stage X tile (148 rows) + W[0], W[1] into pair-buffer 0
    {
        const uint4* sxh = g_xh + ((size_t)b * TROWS + t0) * 8;
        for (int i = tid; i < 1184; i += 256) {
            int r = i >> 3, c2 = i & 7;
            cpa16(xs_h + r * 144 + c2 * 16, sxh + i);
        }
        stage_w(wb_u, 0, tid);
        stage_w(wb_u + WSLOT, 1, tid);
        CP_COMMIT();
    }
    const int L = orig_len[b] - (KW - 1);
    const int strd = L >> 1, kern = (L + 1) >> 1;

    // per-warp ldmatrix base addresses
    uint32_t cA[4];
#pragma unroll
    for (int i = 0; i < 4; i++)
        cA[i] = (uint32_t)((wm * 64 + i * 16 + (lane & 15)) * 144 + ((lane >> 4) * 16));
    uint32_t cB[2];
#pragma unroll
    for (int p = 0; p < 2; p++)
        cB[p] = (uint32_t)((wn * 32 + p * 16 + ((lane >> 4) << 3) + (lane & 7)) * 144 +
                           (((lane >> 3) & 1) * 16));

    float acc[4][4][4];
#pragma unroll
    for (int i = 0; i < 4; i++)
#pragma unroll
        for (int j = 0; j < 4; j++)
#pragma unroll
            for (int e = 0; e < 4; e++) acc[i][j][e] = 0.f;

    CP_WAIT0();
    __syncthreads();

#pragma unroll 1
    for (int kk = 0; kk < KW; kk += 2) {
        const int buf = (kk >> 1) & 1;
        const uint32_t base = wb_u + buf * WPAIR;
        if (kk + 2 < KW) {
            const uint32_t nb = wb_u + (buf ^ 1) * WPAIR;
            stage_w(nb, kk + 2, tid);
            if (kk + 3 < KW) stage_w(nb + WSLOT, kk + 3, tid);
            CP_COMMIT();
        }
#pragma unroll 1
        for (int kq = 0; kq < 2; kq++) {
            const int k = kk + kq;
            if (k >= KW) break;
            const uint32_t axh = xs_h + k * 144;
            const uint32_t bwh = base + kq * WSLOT;
#pragma unroll
            for (int ks = 0; ks < 4; ks++) {
                uint32_t ah[4][4], bh[2][4];
#pragma unroll
                for (int i = 0; i < 4; i++) ldsm4(ah[i], axh + cA[i] + ks * 32);
#pragma unroll
                for (int p = 0; p < 2; p++) ldsm4(bh[p], bwh + cB[p] + ks * 32);
#pragma unroll
                for (int i = 0; i < 4; i++)
#pragma unroll
                    for (int j = 0; j < 4; j++)
                        mma16816(acc[i][j], ah[i], &bh[j >> 1][(j & 1) * 2]);
            }
        }
        CP_WAIT0();
        __syncthreads();
    }

    // Epilogue: acc -> smem [t][n] (stride 136 floats; aliases X+W regions)
    float* ep = (float*)sm;
#pragma unroll
    for (int i = 0; i < 4; i++) {
        int tl = wm * 64 + i * 16 + (lane >> 2);
#pragma unroll
        for (int j = 0; j < 4; j++) {
            int nn = wn * 32 + j * 8 + (lane & 3) * 2;
            *(float2*)&ep[tl * 136 + nn]       = make_float2(acc[i][j][0], acc[i][j][1]);
            *(float2*)&ep[(tl + 8) * 136 + nn] = make_float2(acc[i][j][2], acc[i][j][3]);
        }
    }
    __syncthreads();
    if (tid < 128) {
        float s = 0.f, q = 0.f;
        float m0 = -INFINITY, m1 = -INFINITY, n0 = -INFINITY, n1 = -INFINITY;
        for (int t = 0; t < 128; t++) {
            int tt = t0 + t;
            if (tt < TC) {
                float v = ep[t * 136 + tid];
                s += v; q = fmaf(v, v, q);
                if (tid < 64) {
                    if (tt < kern)               { m0 = fmaxf(m0, v); n0 = fmaxf(n0, -v); }
                    if (tt >= strd && tt < L)    { m1 = fmaxf(m1, v); n1 = fmaxf(n1, -v); }
                }
            }
        }
        atomicAdd(&g_sum[tid], s);
        atomicAdd(&g_sumsq[tid], q);
        if (tid < 64) {
            unsigned* mm = g_mm + (b * 64 + tid) * 4;
            atomicMax(&mm[0], fenc(m0));
            atomicMax(&mm[1], fenc(n0));
            atomicMax(&mm[2], fenc(m1));
            atomicMax(&mm[3], fenc(n1));
        }
    }
    // store avg-branch y (n in [64,128)) as fp16 [b][t][c]
    __half* ybase = g_y2 + ((size_t)b * 16384 + t0) * 64;
    for (int i = tid; i < 2048; i += 256) {
        int t = i >> 4, p4 = i & 15;   // 16 x half4 per row = 64 ch
        float4 v = *(float4*)&ep[t * 136 + 64 + p4 * 4];
        __half2 h0 = __floats2half2_rn(v.x, v.y);
        __half2 h1 = __floats2half2_rn(v.z, v.w);
        uint2 u;
        u.x = *(uint32_t*)&h0;
        u.y = *(uint32_t*)&h1;
        *(uint2*)(ybase + (size_t)t * 64 + p4 * 4) = u;
    }
}

// ---------------------------------------------------------------------------
__global__ void k_stats(const float* __restrict__ g1, const float* __restrict__ b1,
                        const float* __restrict__ g2, const float* __restrict__ b2) {
    int i = threadIdx.x;
    if (i >= 128) return;
    int br = i >> 6, c = i & 63;
    float n = (float)B * (float)TC;
    float mean = g_sum[i] / n;
    float var = g_sumsq[i] / n - mean * mean;
    float gamma = (br == 0) ? g1[c] : g2[c];
    float beta  = (br == 0) ? b1[c] : b2[c];
    float sc = rsqrtf(var + 1e-5f) * gamma;
    g_scale[i] = sc;
    g_shift[i] = beta - mean * sc;
}

// ---------------------------------------------------------------------------
// Avg-branch SPP partial pass over fp16 y2 [b][t][c(64)].
// 256 threads = 32 channel-pairs x 8 t-interleave; TSPLIT blocks per b.
__global__ void __launch_bounds__(256) k_spp(const int* __restrict__ orig_len) {
    const int s = blockIdx.x, b = blockIdx.y;
    const int L = orig_len[b] - (KW - 1);
    const int strd = L >> 1, kern = (L + 1) >> 1;
    const int chunk = (L + TSPLIT - 1) / TSPLIT;
    const int tb = s * chunk;
    const int te = min(L, tb + chunk);
    const int p = threadIdx.x & 31, h = threadIdx.x >> 5;
    const int c0 = 2 * p, c1 = 2 * p + 1;          // avg-branch channel idx
    const float ax = g_scale[64 + c0], ay = g_scale[64 + c1];
    const float sx = g_shift[64 + c0], sy = g_shift[64 + c1];
    const __half2* __restrict__ base =
        (const __half2*)g_y2 + (size_t)b * 16384 * 32 + p;

    float2 sa = make_float2(0.f, 0.f), s0 = sa, s1 = sa;
    for (int t = tb + h; t < te; t += 8) {
        float2 v = __half22float2(base[(size_t)t * 32]);
        v.x = fmaf(v.x, ax, sx); v.y = fmaf(v.y, ay, sy);
        v.x = (v.x > 0.f) ? v.x : 0.01f * v.x;
        v.y = (v.y > 0.f) ? v.y : 0.01f * v.y;
        sa.x += v.x; sa.y += v.y;
        if (t < kern) { s0.x += v.x; s0.y += v.y; }
        if (t >= strd) { s1.x += v.x; s1.y += v.y; }
    }
    __shared__ float2 r0[256], r1[256], r2[256];
    r0[threadIdx.x] = sa; r1[threadIdx.x] = s0; r2[threadIdx.x] = s1;
    __syncthreads();
    if (h == 0) {
#pragma unroll
        for (int g = 1; g < 8; g++) {
            int o = threadIdx.x + g * 32;
            sa.x += r0[o].x; sa.y += r0[o].y;
            s0.x += r1[o].x; s0.y += r1[o].y;
            s1.x += r2[o].x; s1.y += r2[o].y;
        }
        float* pp = g_part + (size_t)(b * TSPLIT + s) * 192;
        pp[c0] = sa.x;        pp[c1] = sa.y;
        pp[64 + c0] = s0.x;   pp[64 + c1] = s0.y;
        pp[128 + c0] = s1.x;  pp[128 + c1] = s1.y;
    }
}

// Finalize: max-branch from g_mm, avg-branch from g_part -> feat -> FC.
__global__ void k_spp2fc(const int* __restrict__ orig_len,
                         const float* __restrict__ fc_w,
                         const float* __restrict__ fc_b,
                         float* __restrict__ out) {
    int b = blockIdx.x, n = threadIdx.x;
    __shared__ float feat[384];
    int L = orig_len[b] - (KW - 1);
    int kern = (L + 1) >> 1;
    if (n < 128) {
        if (n < 64) {
            float a = g_scale[n], sh = g_shift[n];
            const unsigned* mm = g_mm + (b * 64 + n) * 4;
            float M0 = fdec(mm[0]), N0 = -fdec(mm[1]);
            float M1 = fdec(mm[2]), N1 = -fdec(mm[3]);
            float v0 = (a >= 0.f) ? fmaf(a, M0, sh) : fmaf(a, N0, sh);
            float v1 = (a >= 0.f) ? fmaf(a, M1, sh) : fmaf(a, N1, sh);
            v0 = (v0 > 0.f) ? v0 : 0.01f * v0;
            v1 = (v1 > 0.f) ? v1 : 0.01f * v1;
            feat[n] = fmaxf(v0, v1);
            feat[64 + 2 * n] = v0;
            feat[65 + 2 * n] = v1;
        } else {
            int c = n - 64;
            const float* p = g_part + (size_t)b * TSPLIT * 192;
            float sa = 0.f, s0 = 0.f, s1 = 0.f;
            for (int s = 0; s < TSPLIT; s++) {
                sa += p[s * 192 + c];
                s0 += p[s * 192 + 64 + c];
                s1 += p[s * 192 + 128 + c];
            }
            feat[192 + c] = sa / (float)L;
            feat[256 + 2 * c] = s0 / (float)kern;
            feat[257 + 2 * c] = s1 / (float)kern;
        }
    }
    __syncthreads();
    if (n < 64) {
        int task = n >> 5, lane = n & 31;
        float acc = 0.f;
        for (int j = lane; j < 384; j += 32)
            acc = fmaf(feat[j], fc_w[task * 384 + j], acc);
#pragma unroll
        for (int off = 16; off; off >>= 1)
            acc += __shfl_down_sync(0xffffffffu, acc, off);
        if (lane == 0) out[b * 2 + task] = acc + fc_b[task];
    }
}

// ---------------------------------------------------------------------------
extern "C" void kernel_launch(void* const* d_in, const int* in_sizes, int n_in,
                              void* d_out, int out_size) {
    const float* x        = (const float*)d_in[0];
    const int*   orig_len = (const int*)  d_in[1];
    const float* w1       = (const float*)d_in[2];
    const float* g1       = (const float*)d_in[3];
    const float* b1       = (const float*)d_in[4];
    const float* w2       = (const float*)d_in[5];
    const float* g2       = (const float*)d_in[6];
    const float* b2       = (const float*)d_in[7];
    const float* fcw      = (const float*)d_in[8];
    const float* fcb      = (const float*)d_in[9];
    float* out = (float*)d_out;

    cudaFuncSetAttribute(k_conv, cudaFuncAttributeMaxDynamicSharedMemorySize,
                         SMEM_TOTAL);

    k_init<<<1, 128>>>();
    k_prepw<<<21, 256>>>(w1, w2);
    dim3 gx(TROWS / 128, B);
    k_prepx<<<gx, 256>>>(x);
    dim3 gc(NTILES, B);
    k_conv<<<gc, 256, SMEM_TOTAL>>>(orig_len);
    k_stats<<<1, 128>>>(g1, b1, g2, b2);
    dim3 gs(TSPLIT, B);
    k_spp<<<gs, 256>>>(orig_len);
    k_spp2fc<<<B, 128>>>(orig_len, fcw, fcb, out);
}